// round 1
// baseline (speedup 1.0000x reference)
#include <cuda_runtime.h>
#include <math.h>

// Problem constants
#define BB 2
#define SS 2048
#define EE 1024
#define HH 16
#define DD 64
#define MTOT (BB * SS)   // 4096

// Scratch (no allocations allowed): Q,K,V in [B,H,S,D], attn out in [B,S,E]
__device__ float g_Q[BB * HH * SS * DD];
__device__ float g_K[BB * HH * SS * DD];
__device__ float g_V[BB * HH * SS * DD];
__device__ float g_A[BB * SS * EE];

// ---------------------------------------------------------------------------
// GEMM: C[m,n] = sum_k A[m,k] * W[n,k] + bias[n]
// A: [MTOT, EE] row-major, W: [EE, EE] row-major (out-feature major, torch Linear)
// MODE 0: C = [MTOT, EE] plain (final output projection)
// MODE 1: C = [B,H,S,D] head-split layout (QKV projections)
// Tiles: 64x64, K-step 16, 256 threads, 4x4 per-thread micro-tile.
// ---------------------------------------------------------------------------
template <int MODE>
__global__ void __launch_bounds__(256) gemm_bias_kernel(
    const float* __restrict__ A, const float* __restrict__ W,
    const float* __restrict__ bias, float* __restrict__ C)
{
    __shared__ float As[16][64];   // [k][m]
    __shared__ float Ws[16][64];   // [k][n]

    const int tid = threadIdx.x;
    const int tx  = tid & 15;      // m micro index (rows)
    const int ty  = tid >> 4;      // n micro index (cols)
    const int m0  = blockIdx.x * 64;
    const int n0  = blockIdx.y * 64;

    const int lr = tid >> 2;            // 0..63 (row within tile)
    const int lk = (tid & 3) << 2;      // 0,4,8,12 (k float4 offset)

    const float* Ap = A + (size_t)(m0 + lr) * EE + lk;
    const float* Wp = W + (size_t)(n0 + lr) * EE + lk;

    float acc[4][4];
#pragma unroll
    for (int i = 0; i < 4; i++)
#pragma unroll
        for (int j = 0; j < 4; j++) acc[i][j] = 0.0f;

    for (int kt = 0; kt < EE; kt += 16) {
        float4 a = *(const float4*)(Ap + kt);
        float4 w = *(const float4*)(Wp + kt);
        __syncthreads();
        As[lk + 0][lr] = a.x; As[lk + 1][lr] = a.y;
        As[lk + 2][lr] = a.z; As[lk + 3][lr] = a.w;
        Ws[lk + 0][lr] = w.x; Ws[lk + 1][lr] = w.y;
        Ws[lk + 2][lr] = w.z; Ws[lk + 3][lr] = w.w;
        __syncthreads();
#pragma unroll
        for (int k = 0; k < 16; k++) {
            float4 av = *(const float4*)&As[k][tx * 4];
            float4 wv = *(const float4*)&Ws[k][ty * 4];
            float am[4] = {av.x, av.y, av.z, av.w};
            float wn[4] = {wv.x, wv.y, wv.z, wv.w};
#pragma unroll
            for (int i = 0; i < 4; i++)
#pragma unroll
                for (int j = 0; j < 4; j++)
                    acc[i][j] = fmaf(am[i], wn[j], acc[i][j]);
        }
    }

    const int nb = n0 + ty * 4;
    float b0 = bias[nb + 0], b1 = bias[nb + 1], b2 = bias[nb + 2], b3 = bias[nb + 3];
#pragma unroll
    for (int i = 0; i < 4; i++) {
        const int m = m0 + tx * 4 + i;
        if (MODE == 0) {
            float4 r;
            r.x = acc[i][0] + b0; r.y = acc[i][1] + b1;
            r.z = acc[i][2] + b2; r.w = acc[i][3] + b3;
            *(float4*)&C[(size_t)m * EE + nb] = r;
        } else {
            const int b = m >> 11;        // m / SS
            const int s = m & (SS - 1);
            float vals[4] = {acc[i][0] + b0, acc[i][1] + b1,
                             acc[i][2] + b2, acc[i][3] + b3};
#pragma unroll
            for (int j = 0; j < 4; j++) {
                const int n = nb + j;
                const int h = n >> 6;     // n / DD
                const int d = n & 63;
                C[(((size_t)(b * HH + h)) * SS + s) * DD + d] = vals[j];
            }
        }
    }
}

// ---------------------------------------------------------------------------
// Flash attention: one block = 64 query rows for one (b,h).
// Q,K,V: [B,H,S,D]. Output written to [B,S,E] (merged heads, ready for Wo).
// Online softmax over 32 key-tiles of 64. 256 threads, 4x4 micro.
// Dynamic smem: Qt,Kt,Vs,Sb each 64*64 floats = 64 KB total.
// ---------------------------------------------------------------------------
__global__ void __launch_bounds__(256) attn_kernel(
    const float* __restrict__ Q, const float* __restrict__ K,
    const float* __restrict__ V, float* __restrict__ O)
{
    extern __shared__ float sm[];
    float* Qt = sm;            // [k][r] : 64*64
    float* Kt = sm + 4096;     // [k][c]
    float* Vs = sm + 8192;     // [c][d]
    float* Sb = sm + 12288;    // [r][c]
    __shared__ float marr[64], larr[64], mnew[64], alf[64];

    const int tid = threadIdx.x;
    const int rr  = tid >> 4;      // row group (0..15) -> rows rr*4..+3
    const int cc  = tid & 15;      // col group (0..15) -> cols cc*4..+3
    const int qt  = blockIdx.x;    // query tile
    const int bh  = blockIdx.y;    // b*H + h
    const size_t base = (size_t)bh * SS * DD;

    // Load Q tile transposed: Qt[k][r]
#pragma unroll
    for (int i = 0; i < 4; i++) {
        const int fid = tid + i * 256;
        const int r   = fid >> 4;
        const int k4  = (fid & 15) << 2;
        float4 v = *(const float4*)&Q[base + (size_t)(qt * 64 + r) * DD + k4];
        Qt[(k4 + 0) * 64 + r] = v.x;
        Qt[(k4 + 1) * 64 + r] = v.y;
        Qt[(k4 + 2) * 64 + r] = v.z;
        Qt[(k4 + 3) * 64 + r] = v.w;
    }
    if (tid < 64) { marr[tid] = -1e30f; larr[tid] = 0.0f; }

    float o[4][4];
#pragma unroll
    for (int i = 0; i < 4; i++)
#pragma unroll
        for (int j = 0; j < 4; j++) o[i][j] = 0.0f;

    for (int ktile = 0; ktile < SS / 64; ktile++) {
        // Stage K,V tile into registers
        float4 kreg[4], vreg[4];
#pragma unroll
        for (int i = 0; i < 4; i++) {
            const int fid = tid + i * 256;
            const int r   = fid >> 4;
            const int k4  = (fid & 15) << 2;
            kreg[i] = *(const float4*)&K[base + (size_t)(ktile * 64 + r) * DD + k4];
            vreg[i] = *(const float4*)&V[base + (size_t)(ktile * 64 + r) * DD + k4];
        }
        __syncthreads();   // prior iteration finished with Kt/Vs/Sb (and Qt ready)
#pragma unroll
        for (int i = 0; i < 4; i++) {
            const int fid = tid + i * 256;
            const int r   = fid >> 4;
            const int k4  = (fid & 15) << 2;
            Kt[(k4 + 0) * 64 + r] = kreg[i].x;
            Kt[(k4 + 1) * 64 + r] = kreg[i].y;
            Kt[(k4 + 2) * 64 + r] = kreg[i].z;
            Kt[(k4 + 3) * 64 + r] = kreg[i].w;
            *(float4*)&Vs[r * 64 + k4] = vreg[i];
        }
        __syncthreads();

        // Scores: s[i][j] = sum_k Q[r][k]*K[c][k]
        float s[4][4];
#pragma unroll
        for (int i = 0; i < 4; i++)
#pragma unroll
            for (int j = 0; j < 4; j++) s[i][j] = 0.0f;
#pragma unroll 8
        for (int k = 0; k < 64; k++) {
            float4 qv = *(const float4*)&Qt[k * 64 + rr * 4];
            float4 kv = *(const float4*)&Kt[k * 64 + cc * 4];
            float qm[4] = {qv.x, qv.y, qv.z, qv.w};
            float kn[4] = {kv.x, kv.y, kv.z, kv.w};
#pragma unroll
            for (int i = 0; i < 4; i++)
#pragma unroll
                for (int j = 0; j < 4; j++)
                    s[i][j] = fmaf(qm[i], kn[j], s[i][j]);
        }
#pragma unroll
        for (int i = 0; i < 4; i++) {
            float4 t;
            t.x = s[i][0] * 0.125f; t.y = s[i][1] * 0.125f;
            t.z = s[i][2] * 0.125f; t.w = s[i][3] * 0.125f;
            *(float4*)&Sb[(rr * 4 + i) * 64 + cc * 4] = t;
        }
        __syncthreads();

        // Row max + rescale factors
        if (tid < 64) {
            float tm = -1e30f;
            for (int c = 0; c < 64; c++) tm = fmaxf(tm, Sb[tid * 64 + c]);
            const float mo = marr[tid];
            const float mn = fmaxf(mo, tm);
            mnew[tid] = mn;
            alf[tid]  = __expf(mo - mn);
            marr[tid] = mn;
        }
        __syncthreads();

        // Exponentiate in place
#pragma unroll
        for (int i = 0; i < 4; i++) {
            const int r = rr * 4 + i;
            const float mn = mnew[r];
            float4 p = *(float4*)&Sb[r * 64 + cc * 4];
            p.x = __expf(p.x - mn); p.y = __expf(p.y - mn);
            p.z = __expf(p.z - mn); p.w = __expf(p.w - mn);
            *(float4*)&Sb[r * 64 + cc * 4] = p;
        }
        __syncthreads();

        // Row sums
        if (tid < 64) {
            float sum = 0.0f;
            for (int c = 0; c < 64; c++) sum += Sb[tid * 64 + c];
            larr[tid] = larr[tid] * alf[tid] + sum;
        }

        // Rescale accumulators and accumulate P*V
#pragma unroll
        for (int i = 0; i < 4; i++) {
            const float a = alf[rr * 4 + i];
            o[i][0] *= a; o[i][1] *= a; o[i][2] *= a; o[i][3] *= a;
        }
#pragma unroll 4
        for (int c = 0; c < 64; c++) {
            float4 v = *(const float4*)&Vs[c * 64 + cc * 4];
#pragma unroll
            for (int i = 0; i < 4; i++) {
                const float p = Sb[(rr * 4 + i) * 64 + c];
                o[i][0] = fmaf(p, v.x, o[i][0]);
                o[i][1] = fmaf(p, v.y, o[i][1]);
                o[i][2] = fmaf(p, v.z, o[i][2]);
                o[i][3] = fmaf(p, v.w, o[i][3]);
            }
        }
    }
    __syncthreads();  // larr final values visible

    const int b = bh >> 4;
    const int h = bh & 15;
#pragma unroll
    for (int i = 0; i < 4; i++) {
        const int r = rr * 4 + i;
        const float inv = 1.0f / larr[r];
        const int srow = qt * 64 + r;
        float4 t;
        t.x = o[i][0] * inv; t.y = o[i][1] * inv;
        t.z = o[i][2] * inv; t.w = o[i][3] * inv;
        *(float4*)&O[((size_t)(b * SS + srow)) * EE + h * DD + cc * 4] = t;
    }
}

// ---------------------------------------------------------------------------
// Launch
// ---------------------------------------------------------------------------
extern "C" void kernel_launch(void* const* d_in, const int* in_sizes, int n_in,
                              void* d_out, int out_size)
{
    const float* query = (const float*)d_in[0];
    const float* key   = (const float*)d_in[1];
    const float* value = (const float*)d_in[2];
    const float* Wq    = (const float*)d_in[3];
    const float* bq    = (const float*)d_in[4];
    const float* Wk    = (const float*)d_in[5];
    const float* bk    = (const float*)d_in[6];
    const float* Wv    = (const float*)d_in[7];
    const float* bv    = (const float*)d_in[8];
    const float* Wo    = (const float*)d_in[9];
    const float* bo    = (const float*)d_in[10];
    float* out = (float*)d_out;

    float *Qb, *Kb, *Vb, *Ab;
    cudaGetSymbolAddress((void**)&Qb, g_Q);
    cudaGetSymbolAddress((void**)&Kb, g_K);
    cudaGetSymbolAddress((void**)&Vb, g_V);
    cudaGetSymbolAddress((void**)&Ab, g_A);

    const int smem_attn = 4 * 64 * 64 * (int)sizeof(float);  // 64 KB
    cudaFuncSetAttribute(attn_kernel, cudaFuncAttributeMaxDynamicSharedMemorySize,
                         smem_attn);

    dim3 ggrid(MTOT / 64, EE / 64);  // 64 x 16
    gemm_bias_kernel<1><<<ggrid, 256>>>(query, Wq, bq, Qb);
    gemm_bias_kernel<1><<<ggrid, 256>>>(key,   Wk, bk, Kb);
    gemm_bias_kernel<1><<<ggrid, 256>>>(value, Wv, bv, Vb);

    dim3 agrid(SS / 64, BB * HH);    // 32 x 32
    attn_kernel<<<agrid, 256, smem_attn>>>(Qb, Kb, Vb, Ab);

    gemm_bias_kernel<0><<<ggrid, 256>>>(Ab, Wo, bo, out);
}

// round 6
// speedup vs baseline: 1.6001x; 1.6001x over previous
#include <cuda_runtime.h>
#include <cstdint>
#include <math.h>

// Problem constants
#define BB 2
#define SS 2048
#define EE 1024
#define HH 16
#define DD 64
#define MTOT (BB * SS)          // 4096
#define NX (MTOT * EE)          // 4194304 floats per activation tensor
#define NW (EE * EE)            // 1048576 floats per weight

// Scratch arena (device globals = sanctioned no-alloc scratch). Floats:
//  [0,NX)      Q   [B,H,S,D]
//  [NX,2NX)    K
//  [2NX,3NX)   V
//  [3NX,4NX)   A   (attention out, [B,S,E])
//  [4NX,7NX)   XC  (tf32-rounded query,key,value)
//  [7NX,8NX)   AC  (tf32-rounded A)
//  [8NX,+4NW)  WC  (tf32-rounded Wq,Wk,Wv,Wo)
__device__ float g_s[8ull * NX + 4ull * NW];

// ---------------------------------------------------------------------------
// Helpers (compute_103-safe PTX only: mma.sync + cp.async, both sm_80+)
// ---------------------------------------------------------------------------
__device__ __forceinline__ uint32_t smem_u32(const void* p) {
    uint32_t a;
    asm("{ .reg .u64 t; cvta.to.shared.u64 t, %1; cvt.u32.u64 %0, t; }"
        : "=r"(a) : "l"(p));
    return a;
}
__device__ __forceinline__ float tf32_rna(float x) {
    uint32_t u;
    asm("cvt.rna.tf32.f32 %0, %1;" : "=r"(u) : "f"(x));
    return __uint_as_float(u);
}
#define CP_ASYNC16(saddr, gptr)                                                \
    asm volatile("cp.async.cg.shared.global [%0], [%1], 16;"                   \
                 :: "r"(saddr), "l"(gptr))
#define CP_COMMIT() asm volatile("cp.async.commit_group;")
#define CP_WAIT(n)  asm volatile("cp.async.wait_group %0;" :: "n"(n))

__device__ __forceinline__ void mma_tf32(float c[4], const uint32_t a[4],
                                         const uint32_t b[2]) {
    asm volatile(
        "mma.sync.aligned.m16n8k8.row.col.f32.tf32.tf32.f32 "
        "{%0,%1,%2,%3}, {%4,%5,%6,%7}, {%8,%9}, {%0,%1,%2,%3};"
        : "+f"(c[0]), "+f"(c[1]), "+f"(c[2]), "+f"(c[3])
        : "r"(a[0]), "r"(a[1]), "r"(a[2]), "r"(a[3]), "r"(b[0]), "r"(b[1]));
}

// ---------------------------------------------------------------------------
// Elementwise tf32 round-to-nearest (removes HW-truncation bias)
// ---------------------------------------------------------------------------
__global__ void __launch_bounds__(256) cvt_kernel(
    const float* __restrict__ x, float* __restrict__ y)
{
    int i = blockIdx.x * 256 + threadIdx.x;
    float4 v = ((const float4*)x)[i];
    v.x = tf32_rna(v.x); v.y = tf32_rna(v.y);
    v.z = tf32_rna(v.z); v.w = tf32_rna(v.w);
    ((float4*)y)[i] = v;
}

// ---------------------------------------------------------------------------
// TF32 mma.sync GEMM: C[m,n] = sum_k A[m,k]*W[n,k] + bias[n]
// A, W pre-rounded to tf32. CTA tile 128x128, 4 warps (2x2), warp tile 64x64.
// K-chunk 32, double-buffered cp.async. SMEM row stride 36 floats (pad 4):
// conflict-free STS.128 deposits and conflict-free fragment LDS.32.
// MODE 0: C row-major [MTOT,EE]. MODE 1: C in [B,H,S,D] head-split layout.
// ---------------------------------------------------------------------------
#define TILE_F 4608            // 128*36 floats per tile
#define BUF_F  9216            // A tile + W tile
template <int MODE>
__global__ void __launch_bounds__(128) gemm_mma_kernel(
    const float* __restrict__ A, const float* __restrict__ W,
    const float* __restrict__ bias, float* __restrict__ C)
{
    extern __shared__ float sm[];

    const int tid  = threadIdx.x;
    const int wid  = tid >> 5;
    const int lane = tid & 31;
    const int g    = lane >> 2;    // group id (row within fragment)
    const int tk   = lane & 3;     // thread-in-group (k / col pair index)
    const int wm   = wid & 1;      // warp m index
    const int wn   = wid >> 1;     // warp n index
    const int m0   = blockIdx.x * 128;
    const int n0   = blockIdx.y * 128;

    const uint32_t sbase = smem_u32(sm);

    // Per-thread global/smem loader coords: 8 float4 per tile per chunk
    const int lrow = tid >> 3;         // +16 per iter? no: f = tid + i*128
    const int lc4  = (tid & 7) * 4;    // float index of float4 in 32-float row
    (void)lrow;

    float acc[4][8][4];
#pragma unroll
    for (int i = 0; i < 4; ++i)
#pragma unroll
        for (int j = 0; j < 8; ++j)
#pragma unroll
            for (int r = 0; r < 4; ++r) acc[i][j][r] = 0.0f;

    // Issue loads of chunk `c` into buffer b
    auto issue = [&](int c, int b) {
        const int k0 = c * 32;
        const uint32_t sbuf = sbase + (uint32_t)b * (BUF_F * 4);
#pragma unroll
        for (int i = 0; i < 8; ++i) {
            const int f   = tid + i * 128;
            const int row = f >> 3;
            const int c4  = (f & 7) * 4;
            const uint32_t so = (uint32_t)(row * 36 + c4) * 4;
            CP_ASYNC16(sbuf + so, A + (size_t)(m0 + row) * EE + k0 + c4);
            CP_ASYNC16(sbuf + TILE_F * 4 + so,
                       W + (size_t)(n0 + row) * EE + k0 + c4);
        }
        CP_COMMIT();
    };

    issue(0, 0);

    for (int c = 0; c < 32; ++c) {
        const int buf = c & 1;
        if (c < 31) issue(c + 1, buf ^ 1);
        if (c < 31) { CP_WAIT(1); } else { CP_WAIT(0); }
        __syncthreads();

        const float* As = sm + buf * BUF_F;
        const float* Ws = As + TILE_F;

#pragma unroll
        for (int ks = 0; ks < 4; ++ks) {
            uint32_t a[4][4], b[8][2];
            const int kk = ks * 8 + tk;
#pragma unroll
            for (int i = 0; i < 4; ++i) {
                const int r0 = wm * 64 + i * 16 + g;
                a[i][0] = __float_as_uint(As[r0 * 36 + kk]);
                a[i][1] = __float_as_uint(As[(r0 + 8) * 36 + kk]);
                a[i][2] = __float_as_uint(As[r0 * 36 + kk + 4]);
                a[i][3] = __float_as_uint(As[(r0 + 8) * 36 + kk + 4]);
            }
#pragma unroll
            for (int j = 0; j < 8; ++j) {
                const int nr = wn * 64 + j * 8 + g;
                b[j][0] = __float_as_uint(Ws[nr * 36 + kk]);
                b[j][1] = __float_as_uint(Ws[nr * 36 + kk + 4]);
            }
#pragma unroll
            for (int i = 0; i < 4; ++i)
#pragma unroll
                for (int j = 0; j < 8; ++j)
                    mma_tf32(acc[i][j], a[i], b[j]);
        }
        __syncthreads();
    }

    // Epilogue: each thread owns rows (g, g+8) and col pair (2tk, 2tk+1)
#pragma unroll
    for (int i = 0; i < 4; ++i) {
        const int row0 = m0 + wm * 64 + i * 16 + g;
        const int row1 = row0 + 8;
#pragma unroll
        for (int j = 0; j < 8; ++j) {
            const int col = n0 + wn * 64 + j * 8 + 2 * tk;
            const float b0 = bias[col], b1 = bias[col + 1];
            float2 v0, v1;
            v0.x = acc[i][j][0] + b0; v0.y = acc[i][j][1] + b1;
            v1.x = acc[i][j][2] + b0; v1.y = acc[i][j][3] + b1;
            if (MODE == 0) {
                *(float2*)&C[(size_t)row0 * EE + col] = v0;
                *(float2*)&C[(size_t)row1 * EE + col] = v1;
            } else {
                const int h = col >> 6;
                const int d = col & 63;
                const int b0r = row0 >> 11, s0 = row0 & (SS - 1);
                const int b1r = row1 >> 11, s1 = row1 & (SS - 1);
                *(float2*)&C[(((size_t)(b0r * HH + h)) * SS + s0) * DD + d] = v0;
                *(float2*)&C[(((size_t)(b1r * HH + h)) * SS + s1) * DD + d] = v1;
            }
        }
    }
}

// ---------------------------------------------------------------------------
// Flash attention (SIMT fp32 — mma port next round)
// ---------------------------------------------------------------------------
__global__ void __launch_bounds__(256) attn_kernel(
    const float* __restrict__ Q, const float* __restrict__ K,
    const float* __restrict__ V, float* __restrict__ O)
{
    extern __shared__ float smf[];
    float* Qt = smf;           // [k][r] 64x64
    float* Kt = smf + 4096;    // [k][c]
    float* Vs = smf + 8192;    // [c][d]
    float* Sb = smf + 12288;   // [r][c]
    __shared__ float marr[64], larr[64], mnew[64], alf[64];

    const int tid = threadIdx.x;
    const int rr  = tid >> 4;
    const int cc  = tid & 15;
    const int qt  = blockIdx.x;
    const int bh  = blockIdx.y;
    const size_t base = (size_t)bh * SS * DD;

#pragma unroll
    for (int i = 0; i < 4; i++) {
        const int fid = tid + i * 256;
        const int r   = fid >> 4;
        const int k4  = (fid & 15) << 2;
        float4 v = *(const float4*)&Q[base + (size_t)(qt * 64 + r) * DD + k4];
        Qt[(k4 + 0) * 64 + r] = v.x;
        Qt[(k4 + 1) * 64 + r] = v.y;
        Qt[(k4 + 2) * 64 + r] = v.z;
        Qt[(k4 + 3) * 64 + r] = v.w;
    }
    if (tid < 64) { marr[tid] = -1e30f; larr[tid] = 0.0f; }

    float o[4][4];
#pragma unroll
    for (int i = 0; i < 4; i++)
#pragma unroll
        for (int j = 0; j < 4; j++) o[i][j] = 0.0f;

    for (int ktile = 0; ktile < SS / 64; ktile++) {
        float4 kreg[4], vreg[4];
#pragma unroll
        for (int i = 0; i < 4; i++) {
            const int fid = tid + i * 256;
            const int r   = fid >> 4;
            const int k4  = (fid & 15) << 2;
            kreg[i] = *(const float4*)&K[base + (size_t)(ktile * 64 + r) * DD + k4];
            vreg[i] = *(const float4*)&V[base + (size_t)(ktile * 64 + r) * DD + k4];
        }
        __syncthreads();
#pragma unroll
        for (int i = 0; i < 4; i++) {
            const int fid = tid + i * 256;
            const int r   = fid >> 4;
            const int k4  = (fid & 15) << 2;
            Kt[(k4 + 0) * 64 + r] = kreg[i].x;
            Kt[(k4 + 1) * 64 + r] = kreg[i].y;
            Kt[(k4 + 2) * 64 + r] = kreg[i].z;
            Kt[(k4 + 3) * 64 + r] = kreg[i].w;
            *(float4*)&Vs[r * 64 + k4] = vreg[i];
        }
        __syncthreads();

        float s[4][4];
#pragma unroll
        for (int i = 0; i < 4; i++)
#pragma unroll
            for (int j = 0; j < 4; j++) s[i][j] = 0.0f;
#pragma unroll 8
        for (int k = 0; k < 64; k++) {
            float4 qv = *(const float4*)&Qt[k * 64 + rr * 4];
            float4 kv = *(const float4*)&Kt[k * 64 + cc * 4];
            float qm[4] = {qv.x, qv.y, qv.z, qv.w};
            float kn[4] = {kv.x, kv.y, kv.z, kv.w};
#pragma unroll
            for (int i = 0; i < 4; i++)
#pragma unroll
                for (int j = 0; j < 4; j++)
                    s[i][j] = fmaf(qm[i], kn[j], s[i][j]);
        }
#pragma unroll
        for (int i = 0; i < 4; i++) {
            float4 t;
            t.x = s[i][0] * 0.125f; t.y = s[i][1] * 0.125f;
            t.z = s[i][2] * 0.125f; t.w = s[i][3] * 0.125f;
            *(float4*)&Sb[(rr * 4 + i) * 64 + cc * 4] = t;
        }
        __syncthreads();

        if (tid < 64) {
            float tm = -1e30f;
            for (int c = 0; c < 64; c++) tm = fmaxf(tm, Sb[tid * 64 + c]);
            const float mo = marr[tid];
            const float mn = fmaxf(mo, tm);
            mnew[tid] = mn;
            alf[tid]  = __expf(mo - mn);
            marr[tid] = mn;
        }
        __syncthreads();

#pragma unroll
        for (int i = 0; i < 4; i++) {
            const int r = rr * 4 + i;
            const float mn = mnew[r];
            float4 p = *(float4*)&Sb[r * 64 + cc * 4];
            p.x = __expf(p.x - mn); p.y = __expf(p.y - mn);
            p.z = __expf(p.z - mn); p.w = __expf(p.w - mn);
            *(float4*)&Sb[r * 64 + cc * 4] = p;
        }
        __syncthreads();

        if (tid < 64) {
            float sum = 0.0f;
            for (int c = 0; c < 64; c++) sum += Sb[tid * 64 + c];
            larr[tid] = larr[tid] * alf[tid] + sum;
        }

#pragma unroll
        for (int i = 0; i < 4; i++) {
            const float a = alf[rr * 4 + i];
            o[i][0] *= a; o[i][1] *= a; o[i][2] *= a; o[i][3] *= a;
        }
#pragma unroll 4
        for (int c = 0; c < 64; c++) {
            float4 v = *(const float4*)&Vs[c * 64 + cc * 4];
#pragma unroll
            for (int i = 0; i < 4; i++) {
                const float p = Sb[(rr * 4 + i) * 64 + c];
                o[i][0] = fmaf(p, v.x, o[i][0]);
                o[i][1] = fmaf(p, v.y, o[i][1]);
                o[i][2] = fmaf(p, v.z, o[i][2]);
                o[i][3] = fmaf(p, v.w, o[i][3]);
            }
        }
    }
    __syncthreads();

    const int b = bh >> 4;
    const int h = bh & 15;
#pragma unroll
    for (int i = 0; i < 4; i++) {
        const int r = rr * 4 + i;
        const float inv = 1.0f / larr[r];
        const int srow = qt * 64 + r;
        float4 t;
        t.x = o[i][0] * inv; t.y = o[i][1] * inv;
        t.z = o[i][2] * inv; t.w = o[i][3] * inv;
        *(float4*)&O[((size_t)(b * SS + srow)) * EE + h * DD + cc * 4] = t;
    }
}

// ---------------------------------------------------------------------------
// Launch
// ---------------------------------------------------------------------------
extern "C" void kernel_launch(void* const* d_in, const int* in_sizes, int n_in,
                              void* d_out, int out_size)
{
    const float* query = (const float*)d_in[0];
    const float* key   = (const float*)d_in[1];
    const float* value = (const float*)d_in[2];
    const float* Wq    = (const float*)d_in[3];
    const float* bq    = (const float*)d_in[4];
    const float* Wk    = (const float*)d_in[5];
    const float* bk    = (const float*)d_in[6];
    const float* Wv    = (const float*)d_in[7];
    const float* bv    = (const float*)d_in[8];
    const float* Wo    = (const float*)d_in[9];
    const float* bo    = (const float*)d_in[10];
    float* out = (float*)d_out;

    float* S;
    cudaGetSymbolAddress((void**)&S, g_s);
    float* Qb = S;
    float* Kb = S + 1ull * NX;
    float* Vb = S + 2ull * NX;
    float* Ab = S + 3ull * NX;
    float* XC = S + 4ull * NX;          // 3 tensors
    float* AC = S + 7ull * NX;
    float* WC = S + 8ull * NX;          // 4 weights

    const float* Xs[3] = {query, key, value};
    const float* Ws[4] = {Wq, Wk, Wv, Wo};

    for (int i = 0; i < 4; ++i)
        cvt_kernel<<<NW / 4 / 256, 256>>>(Ws[i], WC + (size_t)i * NW);
    for (int i = 0; i < 3; ++i)
        cvt_kernel<<<NX / 4 / 256, 256>>>(Xs[i], XC + (size_t)i * NX);

    const int gemm_smem = 2 * BUF_F * (int)sizeof(float);   // 73728 B
    cudaFuncSetAttribute(gemm_mma_kernel<0>,
                         cudaFuncAttributeMaxDynamicSharedMemorySize, gemm_smem);
    cudaFuncSetAttribute(gemm_mma_kernel<1>,
                         cudaFuncAttributeMaxDynamicSharedMemorySize, gemm_smem);

    dim3 gg(MTOT / 128, EE / 128);  // 32 x 8
    gemm_mma_kernel<1><<<gg, 128, gemm_smem>>>(XC,             WC,             bq, Qb);
    gemm_mma_kernel<1><<<gg, 128, gemm_smem>>>(XC + NX,        WC + NW,        bk, Kb);
    gemm_mma_kernel<1><<<gg, 128, gemm_smem>>>(XC + 2ull * NX, WC + 2ull * NW, bv, Vb);

    const int smem_attn = 4 * 64 * 64 * (int)sizeof(float);  // 64 KB
    cudaFuncSetAttribute(attn_kernel, cudaFuncAttributeMaxDynamicSharedMemorySize,
                         smem_attn);
    dim3 agrid(SS / 64, BB * HH);
    attn_kernel<<<agrid, 256, smem_attn>>>(Qb, Kb, Vb, Ab);

    cvt_kernel<<<NX / 4 / 256, 256>>>(Ab, AC);
    gemm_mma_kernel<0><<<gg, 128, gemm_smem>>>(AC, WC + 3ull * NW, bo, out);
}

// round 7
// speedup vs baseline: 4.6284x; 2.8925x over previous
#include <cuda_runtime.h>
#include <cstdint>
#include <math.h>

// Problem constants
#define BB 2
#define SS 2048
#define EE 1024
#define HH 16
#define DD 64
#define MTOT (BB * SS)          // 4096
#define NX (MTOT * EE)          // 4194304 floats per activation tensor
#define NW (EE * EE)            // 1048576 floats per weight

// Scratch arena. Floats:
//  [0,NX)      Q   [B,H,S,D]  (tf32-rounded by GEMM epilogue)
//  [NX,2NX)    K
//  [2NX,3NX)   V
//  [3NX,4NX)   A   (attention out, [B,S,E], tf32-rounded by attn epilogue)
//  [4NX,7NX)   XC  (tf32-rounded query,key,value)
//  [7NX,8NX)   (unused)
//  [8NX,+4NW)  WC  (tf32-rounded Wq,Wk,Wv,Wo)
__device__ float g_s[8ull * NX + 4ull * NW];

// ---------------------------------------------------------------------------
// Helpers (compute_103-safe: mma.sync + cp.async, both sm_80+ PTX)
// ---------------------------------------------------------------------------
__device__ __forceinline__ uint32_t smem_u32(const void* p) {
    uint32_t a;
    asm("{ .reg .u64 t; cvta.to.shared.u64 t, %1; cvt.u32.u64 %0, t; }"
        : "=r"(a) : "l"(p));
    return a;
}
__device__ __forceinline__ float tf32_rna(float x) {
    uint32_t u;
    asm("cvt.rna.tf32.f32 %0, %1;" : "=r"(u) : "f"(x));
    return __uint_as_float(u);
}
#define CP_ASYNC16(saddr, gptr)                                                \
    asm volatile("cp.async.cg.shared.global [%0], [%1], 16;"                   \
                 :: "r"(saddr), "l"(gptr))
#define CP_COMMIT() asm volatile("cp.async.commit_group;")
#define CP_WAIT(n)  asm volatile("cp.async.wait_group %0;" :: "n"(n))

__device__ __forceinline__ void mma_tf32(float c[4], const uint32_t a[4],
                                         const uint32_t b[2]) {
    asm volatile(
        "mma.sync.aligned.m16n8k8.row.col.f32.tf32.tf32.f32 "
        "{%0,%1,%2,%3}, {%4,%5,%6,%7}, {%8,%9}, {%0,%1,%2,%3};"
        : "+f"(c[0]), "+f"(c[1]), "+f"(c[2]), "+f"(c[3])
        : "r"(a[0]), "r"(a[1]), "r"(a[2]), "r"(a[3]), "r"(b[0]), "r"(b[1]));
}

// ---------------------------------------------------------------------------
// Elementwise tf32 round-to-nearest
// ---------------------------------------------------------------------------
__global__ void __launch_bounds__(256) cvt_kernel(
    const float* __restrict__ x, float* __restrict__ y)
{
    int i = blockIdx.x * 256 + threadIdx.x;
    float4 v = ((const float4*)x)[i];
    v.x = tf32_rna(v.x); v.y = tf32_rna(v.y);
    v.z = tf32_rna(v.z); v.w = tf32_rna(v.w);
    ((float4*)y)[i] = v;
}

// ---------------------------------------------------------------------------
// TF32 mma.sync GEMM (validated in R6): C[m,n] = sum_k A[m,k]*W[n,k] + bias[n]
// MODE 0: C row-major [MTOT,EE] (raw fp32).
// MODE 1: C in [B,H,S,D] head-split layout, tf32-RNA-rounded (feeds attn mma).
// ---------------------------------------------------------------------------
#define TILE_F 4608            // 128*36 floats per tile
#define BUF_F  9216            // A tile + W tile
template <int MODE>
__global__ void __launch_bounds__(128) gemm_mma_kernel(
    const float* __restrict__ A, const float* __restrict__ W,
    const float* __restrict__ bias, float* __restrict__ C)
{
    extern __shared__ float sm[];

    const int tid  = threadIdx.x;
    const int wid  = tid >> 5;
    const int lane = tid & 31;
    const int g    = lane >> 2;
    const int tk   = lane & 3;
    const int wm   = wid & 1;
    const int wn   = wid >> 1;
    const int m0   = blockIdx.x * 128;
    const int n0   = blockIdx.y * 128;

    const uint32_t sbase = smem_u32(sm);

    float acc[4][8][4];
#pragma unroll
    for (int i = 0; i < 4; ++i)
#pragma unroll
        for (int j = 0; j < 8; ++j)
#pragma unroll
            for (int r = 0; r < 4; ++r) acc[i][j][r] = 0.0f;

    auto issue = [&](int c, int b) {
        const int k0 = c * 32;
        const uint32_t sbuf = sbase + (uint32_t)b * (BUF_F * 4);
#pragma unroll
        for (int i = 0; i < 8; ++i) {
            const int f   = tid + i * 128;
            const int row = f >> 3;
            const int c4  = (f & 7) * 4;
            const uint32_t so = (uint32_t)(row * 36 + c4) * 4;
            CP_ASYNC16(sbuf + so, A + (size_t)(m0 + row) * EE + k0 + c4);
            CP_ASYNC16(sbuf + TILE_F * 4 + so,
                       W + (size_t)(n0 + row) * EE + k0 + c4);
        }
        CP_COMMIT();
    };

    issue(0, 0);

    for (int c = 0; c < 32; ++c) {
        const int buf = c & 1;
        if (c < 31) { issue(c + 1, buf ^ 1); CP_WAIT(1); }
        else        { CP_WAIT(0); }
        __syncthreads();

        const float* As = sm + buf * BUF_F;
        const float* Ws = As + TILE_F;

#pragma unroll
        for (int ks = 0; ks < 4; ++ks) {
            uint32_t a[4][4], b[8][2];
            const int kk = ks * 8 + tk;
#pragma unroll
            for (int i = 0; i < 4; ++i) {
                const int r0 = wm * 64 + i * 16 + g;
                a[i][0] = __float_as_uint(As[r0 * 36 + kk]);
                a[i][1] = __float_as_uint(As[(r0 + 8) * 36 + kk]);
                a[i][2] = __float_as_uint(As[r0 * 36 + kk + 4]);
                a[i][3] = __float_as_uint(As[(r0 + 8) * 36 + kk + 4]);
            }
#pragma unroll
            for (int j = 0; j < 8; ++j) {
                const int nr = wn * 64 + j * 8 + g;
                b[j][0] = __float_as_uint(Ws[nr * 36 + kk]);
                b[j][1] = __float_as_uint(Ws[nr * 36 + kk + 4]);
            }
#pragma unroll
            for (int i = 0; i < 4; ++i)
#pragma unroll
                for (int j = 0; j < 8; ++j)
                    mma_tf32(acc[i][j], a[i], b[j]);
        }
        __syncthreads();
    }

#pragma unroll
    for (int i = 0; i < 4; ++i) {
        const int row0 = m0 + wm * 64 + i * 16 + g;
        const int row1 = row0 + 8;
#pragma unroll
        for (int j = 0; j < 8; ++j) {
            const int col = n0 + wn * 64 + j * 8 + 2 * tk;
            const float b0 = bias[col], b1 = bias[col + 1];
            float2 v0, v1;
            v0.x = acc[i][j][0] + b0; v0.y = acc[i][j][1] + b1;
            v1.x = acc[i][j][2] + b0; v1.y = acc[i][j][3] + b1;
            if (MODE == 0) {
                *(float2*)&C[(size_t)row0 * EE + col] = v0;
                *(float2*)&C[(size_t)row1 * EE + col] = v1;
            } else {
                v0.x = tf32_rna(v0.x); v0.y = tf32_rna(v0.y);
                v1.x = tf32_rna(v1.x); v1.y = tf32_rna(v1.y);
                const int h = col >> 6;
                const int d = col & 63;
                const int b0r = row0 >> 11, s0 = row0 & (SS - 1);
                const int b1r = row1 >> 11, s1 = row1 & (SS - 1);
                *(float2*)&C[(((size_t)(b0r * HH + h)) * SS + s0) * DD + d] = v0;
                *(float2*)&C[(((size_t)(b1r * HH + h)) * SS + s1) * DD + d] = v1;
            }
        }
    }
}

// ---------------------------------------------------------------------------
// Flash attention with mma.sync TF32.
// CTA = 128 query rows of one (b,h), 8 warps x 16 rows. Key tiles of 64,
// double-buffered cp.async. Q fragments resident in registers.
// K smem stride 68 (bank-free for QK B-frags), V stride 72 (bank-free for PV).
// Online softmax per row with quad shfl reductions; P routed to A-fragment
// layout by intra-quad shuffles. Output tf32-RNA-rounded (feeds final GEMM).
// ---------------------------------------------------------------------------
#define AKT (64 * 68)          // K tile floats
#define AVT (64 * 72)          // V tile floats
#define AVOFF (2 * AKT)
#define ATTN_SMEM ((2 * AKT + 2 * AVT) * 4)   // 71680 B

__global__ void __launch_bounds__(256) attn_mma_kernel(
    const float* __restrict__ Q, const float* __restrict__ K,
    const float* __restrict__ V, float* __restrict__ O)
{
    extern __shared__ float sm[];
    const int tid  = threadIdx.x;
    const int wid  = tid >> 5;
    const int lane = tid & 31;
    const int g    = lane >> 2;
    const int tk   = lane & 3;
    const int qbse = lane & 28;        // quad base lane
    const int qt   = blockIdx.x;
    const int bh   = blockIdx.y;
    const size_t base = (size_t)bh * SS * DD;

    const uint32_t sb = smem_u32(sm);
    const float Csc = 0.18033688f;     // (1/sqrt(64)) * log2(e)

    // Q fragments: rows qt*128 + wid*16 + {g, g+8}, all 8 k-steps
    uint32_t qf[8][4];
    {
        const float* Qp = Q + base + (size_t)(qt * 128 + wid * 16) * DD;
#pragma unroll
        for (int ks = 0; ks < 8; ++ks) {
            const int kk = ks * 8 + tk;
            qf[ks][0] = __float_as_uint(Qp[g * 64 + kk]);
            qf[ks][1] = __float_as_uint(Qp[(g + 8) * 64 + kk]);
            qf[ks][2] = __float_as_uint(Qp[g * 64 + kk + 4]);
            qf[ks][3] = __float_as_uint(Qp[(g + 8) * 64 + kk + 4]);
        }
    }

    float oa[8][4];
#pragma unroll
    for (int n = 0; n < 8; ++n)
        oa[n][0] = oa[n][1] = oa[n][2] = oa[n][3] = 0.0f;
    float m0 = -1e30f, m1 = -1e30f, l0 = 0.0f, l1 = 0.0f;

    auto issue = [&](int t, int b) {
        const float* Kg = K + base + (size_t)t * 64 * DD;
        const float* Vg = V + base + (size_t)t * 64 * DD;
        const uint32_t kd = sb + (uint32_t)(b * AKT) * 4;
        const uint32_t vd = sb + (uint32_t)(AVOFF + b * AVT) * 4;
#pragma unroll
        for (int i = 0; i < 4; ++i) {
            const int f   = tid + i * 256;
            const int row = f >> 4;
            const int c4  = (f & 15) * 4;
            CP_ASYNC16(kd + (uint32_t)(row * 68 + c4) * 4, Kg + row * 64 + c4);
            CP_ASYNC16(vd + (uint32_t)(row * 72 + c4) * 4, Vg + row * 64 + c4);
        }
        CP_COMMIT();
    };

    issue(0, 0);

    for (int t = 0; t < 32; ++t) {
        const int buf = t & 1;
        if (t < 31) { issue(t + 1, buf ^ 1); CP_WAIT(1); }
        else        { CP_WAIT(0); }
        __syncthreads();

        const float* Kb = sm + buf * AKT;
        const float* Vb = sm + AVOFF + buf * AVT;

        // ---- QK^T ----
        float sa[8][4];
#pragma unroll
        for (int j = 0; j < 8; ++j)
            sa[j][0] = sa[j][1] = sa[j][2] = sa[j][3] = 0.0f;
#pragma unroll
        for (int ks = 0; ks < 8; ++ks) {
            const int kk = ks * 8 + tk;
#pragma unroll
            for (int j = 0; j < 8; ++j) {
                uint32_t b2[2];
                const int kr = (j * 8 + g) * 68 + kk;
                b2[0] = __float_as_uint(Kb[kr]);
                b2[1] = __float_as_uint(Kb[kr + 4]);
                mma_tf32(sa[j], qf[ks], b2);
            }
        }

        // ---- online softmax ----
        float rm0 = -1e30f, rm1 = -1e30f;
#pragma unroll
        for (int j = 0; j < 8; ++j) {
            rm0 = fmaxf(rm0, fmaxf(sa[j][0], sa[j][1]));
            rm1 = fmaxf(rm1, fmaxf(sa[j][2], sa[j][3]));
        }
        rm0 = fmaxf(rm0, __shfl_xor_sync(0xffffffffu, rm0, 1));
        rm0 = fmaxf(rm0, __shfl_xor_sync(0xffffffffu, rm0, 2));
        rm1 = fmaxf(rm1, __shfl_xor_sync(0xffffffffu, rm1, 1));
        rm1 = fmaxf(rm1, __shfl_xor_sync(0xffffffffu, rm1, 2));
        const float mn0 = fmaxf(m0, rm0), mn1 = fmaxf(m1, rm1);
        const float al0 = exp2f((m0 - mn0) * Csc);
        const float al1 = exp2f((m1 - mn1) * Csc);
        m0 = mn0; m1 = mn1;

        float s0 = 0.0f, s1 = 0.0f;
#pragma unroll
        for (int j = 0; j < 8; ++j) {
            sa[j][0] = tf32_rna(exp2f((sa[j][0] - mn0) * Csc)); s0 += sa[j][0];
            sa[j][1] = tf32_rna(exp2f((sa[j][1] - mn0) * Csc)); s0 += sa[j][1];
            sa[j][2] = tf32_rna(exp2f((sa[j][2] - mn1) * Csc)); s1 += sa[j][2];
            sa[j][3] = tf32_rna(exp2f((sa[j][3] - mn1) * Csc)); s1 += sa[j][3];
        }
        s0 += __shfl_xor_sync(0xffffffffu, s0, 1);
        s0 += __shfl_xor_sync(0xffffffffu, s0, 2);
        s1 += __shfl_xor_sync(0xffffffffu, s1, 1);
        s1 += __shfl_xor_sync(0xffffffffu, s1, 2);
        l0 = l0 * al0 + s0;
        l1 = l1 * al1 + s1;
#pragma unroll
        for (int n = 0; n < 8; ++n) {
            oa[n][0] *= al0; oa[n][1] *= al0;
            oa[n][2] *= al1; oa[n][3] *= al1;
        }

        // ---- PV ----
#pragma unroll
        for (int ks = 0; ks < 8; ++ks) {
            const int sl1 = qbse | (tk >> 1);
            const int sl2 = sl1 + 2;
            uint32_t a4[4];
            {
                float v0 = __shfl_sync(0xffffffffu, sa[ks][0], sl1);
                float v1 = __shfl_sync(0xffffffffu, sa[ks][1], sl1);
                float w0 = __shfl_sync(0xffffffffu, sa[ks][0], sl2);
                float w1 = __shfl_sync(0xffffffffu, sa[ks][1], sl2);
                a4[0] = __float_as_uint((tk & 1) ? v1 : v0);
                a4[2] = __float_as_uint((tk & 1) ? w1 : w0);
            }
            {
                float v0 = __shfl_sync(0xffffffffu, sa[ks][2], sl1);
                float v1 = __shfl_sync(0xffffffffu, sa[ks][3], sl1);
                float w0 = __shfl_sync(0xffffffffu, sa[ks][2], sl2);
                float w1 = __shfl_sync(0xffffffffu, sa[ks][3], sl2);
                a4[1] = __float_as_uint((tk & 1) ? v1 : v0);
                a4[3] = __float_as_uint((tk & 1) ? w1 : w0);
            }
#pragma unroll
            for (int n = 0; n < 8; ++n) {
                uint32_t b2[2];
                b2[0] = __float_as_uint(Vb[(ks * 8 + tk) * 72 + n * 8 + g]);
                b2[1] = __float_as_uint(Vb[(ks * 8 + tk + 4) * 72 + n * 8 + g]);
                mma_tf32(oa[n], a4, b2);
            }
        }
        __syncthreads();
    }

    // ---- epilogue: normalize, merge heads into [B,S,E], tf32-round ----
    const float i0 = 1.0f / l0, i1 = 1.0f / l1;
    const int b = bh >> 4, h = bh & 15;
    const int row0 = qt * 128 + wid * 16 + g;
    const int row1 = row0 + 8;
#pragma unroll
    for (int n = 0; n < 8; ++n) {
        const int col = h * 64 + n * 8 + 2 * tk;
        float2 u0, u1;
        u0.x = tf32_rna(oa[n][0] * i0); u0.y = tf32_rna(oa[n][1] * i0);
        u1.x = tf32_rna(oa[n][2] * i1); u1.y = tf32_rna(oa[n][3] * i1);
        *(float2*)&O[((size_t)(b * SS + row0)) * EE + col] = u0;
        *(float2*)&O[((size_t)(b * SS + row1)) * EE + col] = u1;
    }
}

// ---------------------------------------------------------------------------
// Launch
// ---------------------------------------------------------------------------
extern "C" void kernel_launch(void* const* d_in, const int* in_sizes, int n_in,
                              void* d_out, int out_size)
{
    const float* query = (const float*)d_in[0];
    const float* key   = (const float*)d_in[1];
    const float* value = (const float*)d_in[2];
    const float* Wq    = (const float*)d_in[3];
    const float* bq    = (const float*)d_in[4];
    const float* Wk    = (const float*)d_in[5];
    const float* bk    = (const float*)d_in[6];
    const float* Wv    = (const float*)d_in[7];
    const float* bv    = (const float*)d_in[8];
    const float* Wo    = (const float*)d_in[9];
    const float* bo    = (const float*)d_in[10];
    float* out = (float*)d_out;

    float* S;
    cudaGetSymbolAddress((void**)&S, g_s);
    float* Qb = S;
    float* Kb = S + 1ull * NX;
    float* Vb = S + 2ull * NX;
    float* Ab = S + 3ull * NX;
    float* XC = S + 4ull * NX;          // 3 tensors
    float* WC = S + 8ull * NX;          // 4 weights

    const float* Xs[3] = {query, key, value};
    const float* Ws[4] = {Wq, Wk, Wv, Wo};

    for (int i = 0; i < 4; ++i)
        cvt_kernel<<<NW / 4 / 256, 256>>>(Ws[i], WC + (size_t)i * NW);
    for (int i = 0; i < 3; ++i)
        cvt_kernel<<<NX / 4 / 256, 256>>>(Xs[i], XC + (size_t)i * NX);

    const int gemm_smem = 2 * BUF_F * (int)sizeof(float);   // 73728 B
    cudaFuncSetAttribute(gemm_mma_kernel<0>,
                         cudaFuncAttributeMaxDynamicSharedMemorySize, gemm_smem);
    cudaFuncSetAttribute(gemm_mma_kernel<1>,
                         cudaFuncAttributeMaxDynamicSharedMemorySize, gemm_smem);
    cudaFuncSetAttribute(attn_mma_kernel,
                         cudaFuncAttributeMaxDynamicSharedMemorySize, ATTN_SMEM);

    dim3 gg(MTOT / 128, EE / 128);  // 32 x 8
    gemm_mma_kernel<1><<<gg, 128, gemm_smem>>>(XC,             WC,             bq, Qb);
    gemm_mma_kernel<1><<<gg, 128, gemm_smem>>>(XC + NX,        WC + NW,        bk, Kb);
    gemm_mma_kernel<1><<<gg, 128, gemm_smem>>>(XC + 2ull * NX, WC + 2ull * NW, bv, Vb);

    dim3 agrid(SS / 128, BB * HH);  // 16 x 32
    attn_mma_kernel<<<agrid, 256, ATTN_SMEM>>>(Qb, Kb, Vb, Ab);

    // Ab is already tf32-rounded — final GEMM consumes it directly.
    gemm_mma_kernel<0><<<gg, 128, gemm_smem>>>(Ab, WC + 3ull * NW, bo, out);
}

// round 8
// speedup vs baseline: 7.5908x; 1.6401x over previous
#include <cuda_runtime.h>
#include <cuda_fp16.h>
#include <cstdint>
#include <math.h>

// Problem constants
#define BB 2
#define SS 2048
#define EE 1024
#define HH 16
#define DD 64
#define MTOT (BB * SS)          // 4096
#define NX (MTOT * EE)          // 4194304 elems per activation tensor
#define NW (EE * EE)            // 1048576 elems per weight

// fp16 scratch arena (device globals = sanctioned no-alloc scratch). Halves:
//  [0,NX)      Qh  [B,H,S,D]
//  [NX,2NX)    Kh  [B,H,S,D]
//  [2NX,3NX)   Vth [B,H,D,S]  (V transposed)
//  [3NX,4NX)   Ah  [B,S,E]    (attention out)
//  [4NX,7NX)   XC  (f16 query,key,value)
//  [7NX,+4NW)  WC  (f16 Wq,Wk,Wv,Wo)
__device__ __half g_h[7ull * NX + 4ull * NW];

// ---------------------------------------------------------------------------
// Helpers (compute_103-safe: mma.sync fp16 + cp.async, both sm_80+ PTX)
// ---------------------------------------------------------------------------
__device__ __forceinline__ uint32_t smem_u32(const void* p) {
    uint32_t a;
    asm("{ .reg .u64 t; cvta.to.shared.u64 t, %1; cvt.u32.u64 %0, t; }"
        : "=r"(a) : "l"(p));
    return a;
}
#define CP_ASYNC16(saddr, gptr)                                                \
    asm volatile("cp.async.cg.shared.global [%0], [%1], 16;"                   \
                 :: "r"(saddr), "l"(gptr))
#define CP_COMMIT() asm volatile("cp.async.commit_group;")
#define CP_WAIT(n)  asm volatile("cp.async.wait_group %0;" :: "n"(n))

__device__ __forceinline__ void mma_f16(float c[4], const uint32_t a[4],
                                        const uint32_t b[2]) {
    asm volatile(
        "mma.sync.aligned.m16n8k16.row.col.f32.f16.f16.f32 "
        "{%0,%1,%2,%3}, {%4,%5,%6,%7}, {%8,%9}, {%0,%1,%2,%3};"
        : "+f"(c[0]), "+f"(c[1]), "+f"(c[2]), "+f"(c[3])
        : "r"(a[0]), "r"(a[1]), "r"(a[2]), "r"(a[3]), "r"(b[0]), "r"(b[1]));
}
__device__ __forceinline__ uint32_t pack_h2(float lo, float hi) {
    __half2 h = __floats2half2_rn(lo, hi);
    return *(uint32_t*)&h;
}
__device__ __forceinline__ uint32_t ldh2(const __half* p) {
    return *(const uint32_t*)p;
}

// ---------------------------------------------------------------------------
// f32 -> f16 conversion, 8 elems/thread
// ---------------------------------------------------------------------------
__global__ void __launch_bounds__(256) cvt16_kernel(
    const float* __restrict__ x, __half* __restrict__ y)
{
    int i = blockIdx.x * 256 + threadIdx.x;
    float4 a = ((const float4*)x)[2 * i];
    float4 b = ((const float4*)x)[2 * i + 1];
    uint4 u;
    u.x = pack_h2(a.x, a.y); u.y = pack_h2(a.z, a.w);
    u.z = pack_h2(b.x, b.y); u.w = pack_h2(b.z, b.w);
    ((uint4*)y)[i] = u;
}

// ---------------------------------------------------------------------------
// FP16 mma.sync GEMM: C[m,n] = sum_k A[m,k]*W[n,k] + bias[n]
// A,W fp16. CTA 128x128, 4 warps (2x2), warp tile 64x64. K-chunk 32
// (2 k16-steps), double-buffered cp.async. smem stride 40 halves: fragment
// b32 loads hit banks 20g+tk (+8ks,+4) -> conflict-free.
// MODE 0: C f32 row-major [MTOT,EE].
// MODE 1: C f16 [B,H,S,D] head-split.
// MODE 2: C f16 [B,H,D,S] head-split transposed (V^T).
// ---------------------------------------------------------------------------
#define GSTR 40
#define GTILE_H (128 * GSTR)     // 5120 halves per tile
#define GBUF_H (2 * GTILE_H)     // A+W per buffer
#define GEMM_SMEM (2 * GBUF_H * 2)  // bytes = 40960

template <int MODE>
__global__ void __launch_bounds__(128) gemm_f16_kernel(
    const __half* __restrict__ A, const __half* __restrict__ W,
    const float* __restrict__ bias, void* __restrict__ Cv)
{
    extern __shared__ __half sh[];

    const int tid  = threadIdx.x;
    const int wid  = tid >> 5;
    const int lane = tid & 31;
    const int g    = lane >> 2;
    const int tk   = lane & 3;
    const int wm   = wid & 1;
    const int wn   = wid >> 1;
    const int m0   = blockIdx.x * 128;
    const int n0   = blockIdx.y * 128;

    const uint32_t sbase = smem_u32(sh);

    float acc[4][8][4];
#pragma unroll
    for (int i = 0; i < 4; ++i)
#pragma unroll
        for (int j = 0; j < 8; ++j)
#pragma unroll
            for (int r = 0; r < 4; ++r) acc[i][j][r] = 0.0f;

    auto issue = [&](int c, int b) {
        const int k0 = c * 32;
        const uint32_t sbuf = sbase + (uint32_t)b * (GBUF_H * 2);
#pragma unroll
        for (int i = 0; i < 8; ++i) {
            const int f = tid + i * 128;          // 0..1023
            if (f < 512) {
                const int row = f >> 2, c8 = (f & 3) * 8;
                CP_ASYNC16(sbuf + (uint32_t)(row * GSTR + c8) * 2,
                           A + (size_t)(m0 + row) * EE + k0 + c8);
            } else {
                const int f2 = f - 512;
                const int row = f2 >> 2, c8 = (f2 & 3) * 8;
                CP_ASYNC16(sbuf + (uint32_t)(GTILE_H + row * GSTR + c8) * 2,
                           W + (size_t)(n0 + row) * EE + k0 + c8);
            }
        }
        CP_COMMIT();
    };

    issue(0, 0);

    for (int c = 0; c < 32; ++c) {
        const int buf = c & 1;
        if (c < 31) { issue(c + 1, buf ^ 1); CP_WAIT(1); }
        else        { CP_WAIT(0); }
        __syncthreads();

        const __half* As = sh + buf * GBUF_H;
        const __half* Ws = As + GTILE_H;

#pragma unroll
        for (int ks = 0; ks < 2; ++ks) {
            const int kk = ks * 16 + 2 * tk;
            uint32_t a[4][4], b[8][2];
#pragma unroll
            for (int i = 0; i < 4; ++i) {
                const int r0 = wm * 64 + i * 16 + g;
                a[i][0] = ldh2(As + r0 * GSTR + kk);
                a[i][1] = ldh2(As + (r0 + 8) * GSTR + kk);
                a[i][2] = ldh2(As + r0 * GSTR + kk + 8);
                a[i][3] = ldh2(As + (r0 + 8) * GSTR + kk + 8);
            }
#pragma unroll
            for (int j = 0; j < 8; ++j) {
                const int nr = wn * 64 + j * 8 + g;
                b[j][0] = ldh2(Ws + nr * GSTR + kk);
                b[j][1] = ldh2(Ws + nr * GSTR + kk + 8);
            }
#pragma unroll
            for (int i = 0; i < 4; ++i)
#pragma unroll
                for (int j = 0; j < 8; ++j)
                    mma_f16(acc[i][j], a[i], b[j]);
        }
        __syncthreads();
    }

#pragma unroll
    for (int i = 0; i < 4; ++i) {
        const int row0 = m0 + wm * 64 + i * 16 + g;
        const int row1 = row0 + 8;
#pragma unroll
        for (int j = 0; j < 8; ++j) {
            const int col = n0 + wn * 64 + j * 8 + 2 * tk;
            const float b0 = bias[col], b1 = bias[col + 1];
            const float v00 = acc[i][j][0] + b0, v01 = acc[i][j][1] + b1;
            const float v10 = acc[i][j][2] + b0, v11 = acc[i][j][3] + b1;
            if (MODE == 0) {
                float* C = (float*)Cv;
                float2 u0 = {v00, v01}, u1 = {v10, v11};
                *(float2*)&C[(size_t)row0 * EE + col] = u0;
                *(float2*)&C[(size_t)row1 * EE + col] = u1;
            } else if (MODE == 1) {
                __half* C = (__half*)Cv;
                const int h = col >> 6, d = col & 63;
                const int b0r = row0 >> 11, s0 = row0 & (SS - 1);
                const int b1r = row1 >> 11, s1 = row1 & (SS - 1);
                *(uint32_t*)&C[(((size_t)(b0r * HH + h)) * SS + s0) * DD + d] =
                    pack_h2(v00, v01);
                *(uint32_t*)&C[(((size_t)(b1r * HH + h)) * SS + s1) * DD + d] =
                    pack_h2(v10, v11);
            } else {
                __half* C = (__half*)Cv;
                const int h = col >> 6, d = col & 63;
                const int b0r = row0 >> 11, s0 = row0 & (SS - 1);
                const int b1r = row1 >> 11, s1 = row1 & (SS - 1);
                __half* base0 = C + (((size_t)(b0r * HH + h)) * DD + d) * SS;
                __half* base1 = C + (((size_t)(b1r * HH + h)) * DD + d) * SS;
                base0[s0]      = __float2half(v00);
                base0[SS + s0] = __float2half(v01);
                base1[s1]      = __float2half(v10);
                base1[SS + s1] = __float2half(v11);
            }
        }
    }
}

// ---------------------------------------------------------------------------
// FP16 flash attention.
// CTA = 128 query rows of one (b,h), 8 warps x 16 rows. Key tiles of 64,
// double-buffered cp.async. Q frags in registers. K smem [key][dim],
// V^T smem [d][key], both stride 72 halves (frag bank = 4g+tk, bijective).
// QK C-frags ARE PV A-frags after f32->h2 packing (no shuffles).
// Output f16 [B,S,E].
// ---------------------------------------------------------------------------
#define AST 72
#define ATILE_H (64 * AST)       // 4608 halves per tile
#define ATTN_SMEM (4 * ATILE_H * 2)   // K0,K1,V0,V1 = 36864 B

__global__ void __launch_bounds__(256) attn_mma_kernel(
    const __half* __restrict__ Q, const __half* __restrict__ K,
    const __half* __restrict__ Vt, __half* __restrict__ O)
{
    extern __shared__ __half sh[];
    const int tid  = threadIdx.x;
    const int wid  = tid >> 5;
    const int lane = tid & 31;
    const int g    = lane >> 2;
    const int tk   = lane & 3;
    const int qt   = blockIdx.x;
    const int bh   = blockIdx.y;
    const size_t base = (size_t)bh * SS * DD;   // same for K and Vt (D*S==S*D)

    const uint32_t sb = smem_u32(sh);
    const float Csc = 0.18033688f;     // (1/sqrt(64)) * log2(e)

    // Q fragments: rows qt*128 + wid*16 + {g,g+8}, 4 k16-steps
    uint32_t qf[4][4];
    {
        const __half* Qp = Q + base + (size_t)(qt * 128 + wid * 16) * DD;
#pragma unroll
        for (int ks = 0; ks < 4; ++ks) {
            const int kk = ks * 16 + 2 * tk;
            qf[ks][0] = ldh2(Qp + g * 64 + kk);
            qf[ks][1] = ldh2(Qp + (g + 8) * 64 + kk);
            qf[ks][2] = ldh2(Qp + g * 64 + kk + 8);
            qf[ks][3] = ldh2(Qp + (g + 8) * 64 + kk + 8);
        }
    }

    float oa[8][4];
#pragma unroll
    for (int n = 0; n < 8; ++n)
        oa[n][0] = oa[n][1] = oa[n][2] = oa[n][3] = 0.0f;
    float m0 = -1e30f, m1 = -1e30f, l0 = 0.0f, l1 = 0.0f;

    auto issue = [&](int t, int b) {
        const __half* Kg = K + base + (size_t)t * 64 * DD;
        const __half* Vg = Vt + base + (size_t)t * 64;   // row d: [d*SS + s]
        const uint32_t kd = sb + (uint32_t)(b * ATILE_H) * 2;
        const uint32_t vd = sb + (uint32_t)((2 + b) * ATILE_H) * 2;
#pragma unroll
        for (int i = 0; i < 4; ++i) {
            const int f = tid + i * 256;      // 0..1023
            if (f < 512) {
                const int row = f >> 3, c8 = (f & 7) * 8;
                CP_ASYNC16(kd + (uint32_t)(row * AST + c8) * 2,
                           Kg + row * 64 + c8);
            } else {
                const int f2 = f - 512;
                const int row = f2 >> 3, c8 = (f2 & 7) * 8;
                CP_ASYNC16(vd + (uint32_t)(row * AST + c8) * 2,
                           Vg + (size_t)row * SS + c8);
            }
        }
        CP_COMMIT();
    };

    issue(0, 0);

    for (int t = 0; t < 32; ++t) {
        const int buf = t & 1;
        if (t < 31) { issue(t + 1, buf ^ 1); CP_WAIT(1); }
        else        { CP_WAIT(0); }
        __syncthreads();

        const __half* Kb = sh + buf * ATILE_H;
        const __half* Vb = sh + (2 + buf) * ATILE_H;

        // ---- QK^T ----
        float sa[8][4];
#pragma unroll
        for (int j = 0; j < 8; ++j)
            sa[j][0] = sa[j][1] = sa[j][2] = sa[j][3] = 0.0f;
#pragma unroll
        for (int ks = 0; ks < 4; ++ks) {
            const int kk = ks * 16 + 2 * tk;
#pragma unroll
            for (int j = 0; j < 8; ++j) {
                uint32_t b2[2];
                const __half* kp = Kb + (j * 8 + g) * AST + kk;
                b2[0] = ldh2(kp);
                b2[1] = ldh2(kp + 8);
                mma_f16(sa[j], qf[ks], b2);
            }
        }

        // ---- online softmax (raw scores; scale folded into exp2 arg) ----
        float rm0 = -1e30f, rm1 = -1e30f;
#pragma unroll
        for (int j = 0; j < 8; ++j) {
            rm0 = fmaxf(rm0, fmaxf(sa[j][0], sa[j][1]));
            rm1 = fmaxf(rm1, fmaxf(sa[j][2], sa[j][3]));
        }
        rm0 = fmaxf(rm0, __shfl_xor_sync(0xffffffffu, rm0, 1));
        rm0 = fmaxf(rm0, __shfl_xor_sync(0xffffffffu, rm0, 2));
        rm1 = fmaxf(rm1, __shfl_xor_sync(0xffffffffu, rm1, 1));
        rm1 = fmaxf(rm1, __shfl_xor_sync(0xffffffffu, rm1, 2));
        const float mn0 = fmaxf(m0, rm0), mn1 = fmaxf(m1, rm1);
        const float al0 = exp2f((m0 - mn0) * Csc);
        const float al1 = exp2f((m1 - mn1) * Csc);
        m0 = mn0; m1 = mn1;

        float s0 = 0.0f, s1 = 0.0f;
#pragma unroll
        for (int j = 0; j < 8; ++j) {
            sa[j][0] = exp2f((sa[j][0] - mn0) * Csc); s0 += sa[j][0];
            sa[j][1] = exp2f((sa[j][1] - mn0) * Csc); s0 += sa[j][1];
            sa[j][2] = exp2f((sa[j][2] - mn1) * Csc); s1 += sa[j][2];
            sa[j][3] = exp2f((sa[j][3] - mn1) * Csc); s1 += sa[j][3];
        }
        s0 += __shfl_xor_sync(0xffffffffu, s0, 1);
        s0 += __shfl_xor_sync(0xffffffffu, s0, 2);
        s1 += __shfl_xor_sync(0xffffffffu, s1, 1);
        s1 += __shfl_xor_sync(0xffffffffu, s1, 2);
        l0 = l0 * al0 + s0;
        l1 = l1 * al1 + s1;
#pragma unroll
        for (int n = 0; n < 8; ++n) {
            oa[n][0] *= al0; oa[n][1] *= al0;
            oa[n][2] *= al1; oa[n][3] *= al1;
        }

        // ---- P: QK C-frag -> fp16 A-frag (pure packing, no shuffles) ----
        uint32_t pa[4][4];
#pragma unroll
        for (int ks = 0; ks < 4; ++ks) {
            pa[ks][0] = pack_h2(sa[2 * ks][0],     sa[2 * ks][1]);
            pa[ks][1] = pack_h2(sa[2 * ks][2],     sa[2 * ks][3]);
            pa[ks][2] = pack_h2(sa[2 * ks + 1][0], sa[2 * ks + 1][1]);
            pa[ks][3] = pack_h2(sa[2 * ks + 1][2], sa[2 * ks + 1][3]);
        }

        // ---- PV ----
#pragma unroll
        for (int ks = 0; ks < 4; ++ks) {
            const int kk = ks * 16 + 2 * tk;
#pragma unroll
            for (int n = 0; n < 8; ++n) {
                uint32_t b2[2];
                const __half* vp = Vb + (n * 8 + g) * AST + kk;
                b2[0] = ldh2(vp);
                b2[1] = ldh2(vp + 8);
                mma_f16(oa[n], pa[ks], b2);
            }
        }
        __syncthreads();
    }

    // ---- epilogue: normalize, merge heads into f16 [B,S,E] ----
    const float i0 = 1.0f / l0, i1 = 1.0f / l1;
    const int b = bh >> 4, h = bh & 15;
    const int row0 = qt * 128 + wid * 16 + g;
    const int row1 = row0 + 8;
#pragma unroll
    for (int n = 0; n < 8; ++n) {
        const int col = h * 64 + n * 8 + 2 * tk;
        *(uint32_t*)&O[((size_t)(b * SS + row0)) * EE + col] =
            pack_h2(oa[n][0] * i0, oa[n][1] * i0);
        *(uint32_t*)&O[((size_t)(b * SS + row1)) * EE + col] =
            pack_h2(oa[n][2] * i1, oa[n][3] * i1);
    }
}

// ---------------------------------------------------------------------------
// Launch
// ---------------------------------------------------------------------------
extern "C" void kernel_launch(void* const* d_in, const int* in_sizes, int n_in,
                              void* d_out, int out_size)
{
    const float* query = (const float*)d_in[0];
    const float* key   = (const float*)d_in[1];
    const float* value = (const float*)d_in[2];
    const float* Wq    = (const float*)d_in[3];
    const float* bq    = (const float*)d_in[4];
    const float* Wk    = (const float*)d_in[5];
    const float* bk    = (const float*)d_in[6];
    const float* Wv    = (const float*)d_in[7];
    const float* bv    = (const float*)d_in[8];
    const float* Wo    = (const float*)d_in[9];
    const float* bo    = (const float*)d_in[10];
    float* out = (float*)d_out;

    __half* S;
    cudaGetSymbolAddress((void**)&S, g_h);
    __half* Qh  = S;
    __half* Kh  = S + 1ull * NX;
    __half* Vth = S + 2ull * NX;
    __half* Ah  = S + 3ull * NX;
    __half* XC  = S + 4ull * NX;        // 3 tensors
    __half* WC  = S + 7ull * NX;        // 4 weights

    const float* Xs[3] = {query, key, value};
    const float* Ws[4] = {Wq, Wk, Wv, Wo};

    for (int i = 0; i < 4; ++i)
        cvt16_kernel<<<NW / 8 / 256, 256>>>(Ws[i], WC + (size_t)i * NW);
    for (int i = 0; i < 3; ++i)
        cvt16_kernel<<<NX / 8 / 256, 256>>>(Xs[i], XC + (size_t)i * NX);

    cudaFuncSetAttribute(gemm_f16_kernel<0>,
                         cudaFuncAttributeMaxDynamicSharedMemorySize, GEMM_SMEM);
    cudaFuncSetAttribute(gemm_f16_kernel<1>,
                         cudaFuncAttributeMaxDynamicSharedMemorySize, GEMM_SMEM);
    cudaFuncSetAttribute(gemm_f16_kernel<2>,
                         cudaFuncAttributeMaxDynamicSharedMemorySize, GEMM_SMEM);
    cudaFuncSetAttribute(attn_mma_kernel,
                         cudaFuncAttributeMaxDynamicSharedMemorySize, ATTN_SMEM);

    dim3 gg(MTOT / 128, EE / 128);  // 32 x 8
    gemm_f16_kernel<1><<<gg, 128, GEMM_SMEM>>>(XC,             WC,             bq, Qh);
    gemm_f16_kernel<1><<<gg, 128, GEMM_SMEM>>>(XC + NX,        WC + NW,        bk, Kh);
    gemm_f16_kernel<2><<<gg, 128, GEMM_SMEM>>>(XC + 2ull * NX, WC + 2ull * NW, bv, Vth);

    dim3 agrid(SS / 128, BB * HH);  // 16 x 32
    attn_mma_kernel<<<agrid, 256, ATTN_SMEM>>>(Qh, Kh, Vth, Ah);

    gemm_f16_kernel<0><<<gg, 128, GEMM_SMEM>>>(Ah, WC + 3ull * NW, bo, out);
}

// round 10
// speedup vs baseline: 8.6368x; 1.1378x over previous
#include <cuda_runtime.h>
#include <cuda_fp16.h>
#include <cstdint>
#include <math.h>

// Problem constants
#define BB 2
#define SS 2048
#define EE 1024
#define HH 16
#define DD 64
#define MTOT (BB * SS)          // 4096
#define NX (MTOT * EE)          // 4194304 elems per activation tensor
#define NW (EE * EE)            // 1048576 elems per weight

// fp16 scratch arena. Halves:
//  [0,NX)      Qh  [B,H,S,D]
//  [NX,2NX)    Kh  [B,H,S,D]
//  [2NX,3NX)   Vth [B,H,D,S]  (V transposed)
//  [3NX,4NX)   Ah  [B,S,E]    (attention out)
//  [4NX,7NX)   XC  (f16 query,key,value)
//  [7NX,+4NW)  WC  (f16 Wq,Wk,Wv,Wo)
__device__ __half g_h[7ull * NX + 4ull * NW];

// ---------------------------------------------------------------------------
// Helpers (compute_103-safe: mma.sync fp16 + cp.async + ldmatrix, all sm_80- PTX)
// ---------------------------------------------------------------------------
__device__ __forceinline__ uint32_t smem_u32(const void* p) {
    uint32_t a;
    asm("{ .reg .u64 t; cvta.to.shared.u64 t, %1; cvt.u32.u64 %0, t; }"
        : "=r"(a) : "l"(p));
    return a;
}
#define CP_ASYNC16(saddr, gptr)                                                \
    asm volatile("cp.async.cg.shared.global [%0], [%1], 16;"                   \
                 :: "r"(saddr), "l"(gptr))
#define CP_COMMIT() asm volatile("cp.async.commit_group;")
#define CP_WAIT(n)  asm volatile("cp.async.wait_group %0;" :: "n"(n))

__device__ __forceinline__ void mma_f16(float c[4], const uint32_t a[4],
                                        const uint32_t b[2]) {
    asm volatile(
        "mma.sync.aligned.m16n8k16.row.col.f32.f16.f16.f32 "
        "{%0,%1,%2,%3}, {%4,%5,%6,%7}, {%8,%9}, {%0,%1,%2,%3};"
        : "+f"(c[0]), "+f"(c[1]), "+f"(c[2]), "+f"(c[3])
        : "r"(a[0]), "r"(a[1]), "r"(a[2]), "r"(a[3]), "r"(b[0]), "r"(b[1]));
}
__device__ __forceinline__ void ldsm_x4(uint32_t& r0, uint32_t& r1,
                                        uint32_t& r2, uint32_t& r3,
                                        uint32_t addr) {
    asm volatile("ldmatrix.sync.aligned.m8n8.x4.shared.b16 {%0,%1,%2,%3}, [%4];"
                 : "=r"(r0), "=r"(r1), "=r"(r2), "=r"(r3) : "r"(addr));
}
__device__ __forceinline__ uint32_t pack_h2(float lo, float hi) {
    __half2 h = __floats2half2_rn(lo, hi);
    return *(uint32_t*)&h;
}
__device__ __forceinline__ uint32_t ldh2(const __half* p) {
    return *(const uint32_t*)p;
}

// ---------------------------------------------------------------------------
// Batched f32 -> f16 conversion: blockIdx.y selects tensor
// ---------------------------------------------------------------------------
struct Ptr4 { const float* p[4]; };

__global__ void __launch_bounds__(256) cvt16_multi(
    Ptr4 srcs, __half* __restrict__ dst, int elems)
{
    const float* x = srcs.p[blockIdx.y];
    __half* y = dst + (size_t)blockIdx.y * elems;
    int i = blockIdx.x * 256 + threadIdx.x;
    float4 a = ((const float4*)x)[2 * i];
    float4 b = ((const float4*)x)[2 * i + 1];
    uint4 u;
    u.x = pack_h2(a.x, a.y); u.y = pack_h2(a.z, a.w);
    u.z = pack_h2(b.x, b.y); u.w = pack_h2(b.z, b.w);
    ((uint4*)y)[i] = u;
}

// ---------------------------------------------------------------------------
// FP16 mma.sync GEMM with ldmatrix: C[m,n] = sum_k A[m,k]*W[n,k] + bias[n]
// CTA 128x128, 4 warps (2x2), warp tile 64x64. K-chunk 64 (4 k16-steps),
// double-buffered cp.async, 16 chunks. smem stride 72 halves (144B):
// ldmatrix 8-row phases hit 16B groups {0,16,...,112} -> conflict-free.
// MODE 0: C f32 row-major. MODE 1: C f16 [B,H,S,D]. MODE 2: f16 [B,H,D,S].
// ---------------------------------------------------------------------------
#define GSTR 72
#define GTILE_H (128 * GSTR)        // 9216 halves per tile
#define GBUF_H (2 * GTILE_H)        // A+W per buffer
#define GEMM_SMEM (2 * GBUF_H * 2)  // 73728 B

template <int MODE>
__global__ void __launch_bounds__(128) gemm_f16_kernel(
    const __half* __restrict__ A, const __half* __restrict__ W,
    const float* __restrict__ bias, void* __restrict__ Cv)
{
    extern __shared__ __half sh[];

    const int tid  = threadIdx.x;
    const int wid  = tid >> 5;
    const int lane = tid & 31;
    const int g    = lane >> 2;
    const int tk   = lane & 3;
    const int wm   = wid & 1;
    const int wn   = wid >> 1;
    const int m0   = blockIdx.x * 128;
    const int n0   = blockIdx.y * 128;

    const uint32_t sbase = smem_u32(sh);
    // ldmatrix lane->row/col offsets
    const int a_ro = (lane & 7) + ((lane >> 3) & 1) * 8;  // A: mats {r,r+8,r,r+8}
    const int a_co = (lane >> 4) * 8;                     //    cols {0,0,8,8}
    const int b_ro = (lane & 7) + (lane >> 4) * 8;        // B: mats {n,n,n+8,n+8}
    const int b_co = ((lane >> 3) & 1) * 8;               //    cols {0,8,0,8}

    float acc[4][8][4];
#pragma unroll
    for (int i = 0; i < 4; ++i)
#pragma unroll
        for (int j = 0; j < 8; ++j)
#pragma unroll
            for (int r = 0; r < 4; ++r) acc[i][j][r] = 0.0f;

    auto issue = [&](int c, int b) {
        const int k0 = c * 64;
        const uint32_t sbuf = sbase + (uint32_t)b * (GBUF_H * 2);
#pragma unroll
        for (int i = 0; i < 16; ++i) {
            const int f = tid + i * 128;          // 0..2047
            if (f < 1024) {
                const int row = f >> 3, c8 = (f & 7) * 8;
                CP_ASYNC16(sbuf + (uint32_t)(row * GSTR + c8) * 2,
                           A + (size_t)(m0 + row) * EE + k0 + c8);
            } else {
                const int f2 = f - 1024;
                const int row = f2 >> 3, c8 = (f2 & 7) * 8;
                CP_ASYNC16(sbuf + (uint32_t)(GTILE_H + row * GSTR + c8) * 2,
                           W + (size_t)(n0 + row) * EE + k0 + c8);
            }
        }
        CP_COMMIT();
    };

    issue(0, 0);

    for (int c = 0; c < 16; ++c) {
        const int buf = c & 1;
        if (c < 15) { issue(c + 1, buf ^ 1); CP_WAIT(1); }
        else        { CP_WAIT(0); }
        __syncthreads();

        const uint32_t Abase = sbase + (uint32_t)buf * (GBUF_H * 2);
        const uint32_t Wbase = Abase + GTILE_H * 2;

#pragma unroll
        for (int ks = 0; ks < 4; ++ks) {
            const int kk = ks * 16;
            uint32_t a[4][4], b[8][2];
#pragma unroll
            for (int i = 0; i < 4; ++i) {
                const uint32_t ad = Abase +
                    (uint32_t)((wm * 64 + i * 16 + a_ro) * GSTR + kk + a_co) * 2;
                ldsm_x4(a[i][0], a[i][1], a[i][2], a[i][3], ad);
            }
#pragma unroll
            for (int jp = 0; jp < 4; ++jp) {
                const uint32_t bd = Wbase +
                    (uint32_t)((wn * 64 + jp * 16 + b_ro) * GSTR + kk + b_co) * 2;
                ldsm_x4(b[2 * jp][0], b[2 * jp][1],
                        b[2 * jp + 1][0], b[2 * jp + 1][1], bd);
            }
#pragma unroll
            for (int i = 0; i < 4; ++i)
#pragma unroll
                for (int j = 0; j < 8; ++j)
                    mma_f16(acc[i][j], a[i], b[j]);
        }
        __syncthreads();
    }

#pragma unroll
    for (int i = 0; i < 4; ++i) {
        const int row0 = m0 + wm * 64 + i * 16 + g;
        const int row1 = row0 + 8;
#pragma unroll
        for (int j = 0; j < 8; ++j) {
            const int col = n0 + wn * 64 + j * 8 + 2 * tk;
            const float b0 = bias[col], b1 = bias[col + 1];
            const float v00 = acc[i][j][0] + b0, v01 = acc[i][j][1] + b1;
            const float v10 = acc[i][j][2] + b0, v11 = acc[i][j][3] + b1;
            if (MODE == 0) {
                float* C = (float*)Cv;
                float2 u0 = {v00, v01}, u1 = {v10, v11};
                *(float2*)&C[(size_t)row0 * EE + col] = u0;
                *(float2*)&C[(size_t)row1 * EE + col] = u1;
            } else if (MODE == 1) {
                __half* C = (__half*)Cv;
                const int h = col >> 6, d = col & 63;
                const int b0r = row0 >> 11, s0 = row0 & (SS - 1);
                const int b1r = row1 >> 11, s1 = row1 & (SS - 1);
                *(uint32_t*)&C[(((size_t)(b0r * HH + h)) * SS + s0) * DD + d] =
                    pack_h2(v00, v01);
                *(uint32_t*)&C[(((size_t)(b1r * HH + h)) * SS + s1) * DD + d] =
                    pack_h2(v10, v11);
            } else {
                __half* C = (__half*)Cv;
                const int h = col >> 6, d = col & 63;
                const int b0r = row0 >> 11, s0 = row0 & (SS - 1);
                const int b1r = row1 >> 11, s1 = row1 & (SS - 1);
                __half* base0 = C + (((size_t)(b0r * HH + h)) * DD + d) * SS;
                __half* base1 = C + (((size_t)(b1r * HH + h)) * DD + d) * SS;
                base0[s0]      = __float2half(v00);
                base0[SS + s0] = __float2half(v01);
                base1[s1]      = __float2half(v10);
                base1[SS + s1] = __float2half(v11);
            }
        }
    }
}

// ---------------------------------------------------------------------------
// FP16 flash attention with ldmatrix fragment loads.
// CTA = 128 query rows of one (b,h), 8 warps x 16 rows. Key tiles of 64,
// double-buffered cp.async. Q frags in registers. K smem [key][dim],
// V^T smem [d][key], both stride 72 halves (ldmatrix conflict-free).
// QK C-frags ARE PV A-frags after f32->h2 packing.
// ---------------------------------------------------------------------------
#define AST 72
#define ATILE_H (64 * AST)            // 4608 halves per tile
#define ATTN_SMEM (4 * ATILE_H * 2)   // K0,K1,V0,V1 = 36864 B

__global__ void __launch_bounds__(256) attn_mma_kernel(
    const __half* __restrict__ Q, const __half* __restrict__ K,
    const __half* __restrict__ Vt, __half* __restrict__ O)
{
    extern __shared__ __half sh[];
    const int tid  = threadIdx.x;
    const int wid  = tid >> 5;
    const int lane = tid & 31;
    const int g    = lane >> 2;
    const int tk   = lane & 3;
    const int qt   = blockIdx.x;
    const int bh   = blockIdx.y;
    const size_t base = (size_t)bh * SS * DD;

    const uint32_t sb = smem_u32(sh);
    const float Csc = 0.18033688f;     // (1/sqrt(64)) * log2(e)
    const int b_ro = (lane & 7) + (lane >> 4) * 8;
    const int b_co = ((lane >> 3) & 1) * 8;

    // Q fragments: rows qt*128 + wid*16 + {g,g+8}, 4 k16-steps (global loads)
    uint32_t qf[4][4];
    {
        const __half* Qp = Q + base + (size_t)(qt * 128 + wid * 16) * DD;
#pragma unroll
        for (int ks = 0; ks < 4; ++ks) {
            const int kk = ks * 16 + 2 * tk;
            qf[ks][0] = ldh2(Qp + g * 64 + kk);
            qf[ks][1] = ldh2(Qp + (g + 8) * 64 + kk);
            qf[ks][2] = ldh2(Qp + g * 64 + kk + 8);
            qf[ks][3] = ldh2(Qp + (g + 8) * 64 + kk + 8);
        }
    }

    float oa[8][4];
#pragma unroll
    for (int n = 0; n < 8; ++n)
        oa[n][0] = oa[n][1] = oa[n][2] = oa[n][3] = 0.0f;
    float m0 = -1e30f, m1 = -1e30f, l0 = 0.0f, l1 = 0.0f;

    auto issue = [&](int t, int b) {
        const __half* Kg = K + base + (size_t)t * 64 * DD;
        const __half* Vg = Vt + base + (size_t)t * 64;
        const uint32_t kd = sb + (uint32_t)(b * ATILE_H) * 2;
        const uint32_t vd = sb + (uint32_t)((2 + b) * ATILE_H) * 2;
#pragma unroll
        for (int i = 0; i < 4; ++i) {
            const int f = tid + i * 256;
            if (f < 512) {
                const int row = f >> 3, c8 = (f & 7) * 8;
                CP_ASYNC16(kd + (uint32_t)(row * AST + c8) * 2,
                           Kg + row * 64 + c8);
            } else {
                const int f2 = f - 512;
                const int row = f2 >> 3, c8 = (f2 & 7) * 8;
                CP_ASYNC16(vd + (uint32_t)(row * AST + c8) * 2,
                           Vg + (size_t)row * SS + c8);
            }
        }
        CP_COMMIT();
    };

    issue(0, 0);

    for (int t = 0; t < 32; ++t) {
        const int buf = t & 1;
        if (t < 31) { issue(t + 1, buf ^ 1); CP_WAIT(1); }
        else        { CP_WAIT(0); }
        __syncthreads();

        const uint32_t Kbase = sb + (uint32_t)(buf * ATILE_H) * 2;
        const uint32_t Vbase = sb + (uint32_t)((2 + buf) * ATILE_H) * 2;

        // ---- QK^T ----
        float sa[8][4];
#pragma unroll
        for (int j = 0; j < 8; ++j)
            sa[j][0] = sa[j][1] = sa[j][2] = sa[j][3] = 0.0f;
#pragma unroll
        for (int ks = 0; ks < 4; ++ks) {
            const int kk = ks * 16;
            uint32_t bk[8][2];
#pragma unroll
            for (int jp = 0; jp < 4; ++jp) {
                const uint32_t kdr = Kbase +
                    (uint32_t)((jp * 16 + b_ro) * AST + kk + b_co) * 2;
                ldsm_x4(bk[2 * jp][0], bk[2 * jp][1],
                        bk[2 * jp + 1][0], bk[2 * jp + 1][1], kdr);
            }
#pragma unroll
            for (int j = 0; j < 8; ++j)
                mma_f16(sa[j], qf[ks], bk[j]);
        }

        // ---- online softmax ----
        float rm0 = -1e30f, rm1 = -1e30f;
#pragma unroll
        for (int j = 0; j < 8; ++j) {
            rm0 = fmaxf(rm0, fmaxf(sa[j][0], sa[j][1]));
            rm1 = fmaxf(rm1, fmaxf(sa[j][2], sa[j][3]));
        }
        rm0 = fmaxf(rm0, __shfl_xor_sync(0xffffffffu, rm0, 1));
        rm0 = fmaxf(rm0, __shfl_xor_sync(0xffffffffu, rm0, 2));
        rm1 = fmaxf(rm1, __shfl_xor_sync(0xffffffffu, rm1, 1));
        rm1 = fmaxf(rm1, __shfl_xor_sync(0xffffffffu, rm1, 2));
        const float mn0 = fmaxf(m0, rm0), mn1 = fmaxf(m1, rm1);
        const float al0 = exp2f((m0 - mn0) * Csc);
        const float al1 = exp2f((m1 - mn1) * Csc);
        m0 = mn0; m1 = mn1;

        float s0 = 0.0f, s1 = 0.0f;
#pragma unroll
        for (int j = 0; j < 8; ++j) {
            sa[j][0] = exp2f((sa[j][0] - mn0) * Csc); s0 += sa[j][0];
            sa[j][1] = exp2f((sa[j][1] - mn0) * Csc); s0 += sa[j][1];
            sa[j][2] = exp2f((sa[j][2] - mn1) * Csc); s1 += sa[j][2];
            sa[j][3] = exp2f((sa[j][3] - mn1) * Csc); s1 += sa[j][3];
        }
        s0 += __shfl_xor_sync(0xffffffffu, s0, 1);
        s0 += __shfl_xor_sync(0xffffffffu, s0, 2);
        s1 += __shfl_xor_sync(0xffffffffu, s1, 1);
        s1 += __shfl_xor_sync(0xffffffffu, s1, 2);
        l0 = l0 * al0 + s0;
        l1 = l1 * al1 + s1;
#pragma unroll
        for (int n = 0; n < 8; ++n) {
            oa[n][0] *= al0; oa[n][1] *= al0;
            oa[n][2] *= al1; oa[n][3] *= al1;
        }

        // ---- P: QK C-frag -> fp16 A-frag ----
        uint32_t pa[4][4];
#pragma unroll
        for (int ks = 0; ks < 4; ++ks) {
            pa[ks][0] = pack_h2(sa[2 * ks][0],     sa[2 * ks][1]);
            pa[ks][1] = pack_h2(sa[2 * ks][2],     sa[2 * ks][3]);
            pa[ks][2] = pack_h2(sa[2 * ks + 1][0], sa[2 * ks + 1][1]);
            pa[ks][3] = pack_h2(sa[2 * ks + 1][2], sa[2 * ks + 1][3]);
        }

        // ---- PV ----
#pragma unroll
        for (int ks = 0; ks < 4; ++ks) {
            const int kk = ks * 16;
            uint32_t bv[8][2];
#pragma unroll
            for (int jp = 0; jp < 4; ++jp) {
                const uint32_t vdr = Vbase +
                    (uint32_t)((jp * 16 + b_ro) * AST + kk + b_co) * 2;
                ldsm_x4(bv[2 * jp][0], bv[2 * jp][1],
                        bv[2 * jp + 1][0], bv[2 * jp + 1][1], vdr);
            }
#pragma unroll
            for (int n = 0; n < 8; ++n)
                mma_f16(oa[n], pa[ks], bv[n]);
        }
        __syncthreads();
    }

    // ---- epilogue: normalize, merge heads into f16 [B,S,E] ----
    const float i0 = 1.0f / l0, i1 = 1.0f / l1;
    const int b = bh >> 4, h = bh & 15;
    const int row0 = qt * 128 + wid * 16 + g;
    const int row1 = row0 + 8;
#pragma unroll
    for (int n = 0; n < 8; ++n) {
        const int col = h * 64 + n * 8 + 2 * tk;
        *(uint32_t*)&O[((size_t)(b * SS + row0)) * EE + col] =
            pack_h2(oa[n][0] * i0, oa[n][1] * i0);
        *(uint32_t*)&O[((size_t)(b * SS + row1)) * EE + col] =
            pack_h2(oa[n][2] * i1, oa[n][3] * i1);
    }
}

// ---------------------------------------------------------------------------
// Launch
// ---------------------------------------------------------------------------
extern "C" void kernel_launch(void* const* d_in, const int* in_sizes, int n_in,
                              void* d_out, int out_size)
{
    const float* query = (const float*)d_in[0];
    const float* key   = (const float*)d_in[1];
    const float* value = (const float*)d_in[2];
    const float* Wq    = (const float*)d_in[3];
    const float* bq    = (const float*)d_in[4];
    const float* Wk    = (const float*)d_in[5];
    const float* bk    = (const float*)d_in[6];
    const float* Wv    = (const float*)d_in[7];
    const float* bv    = (const float*)d_in[8];
    const float* Wo    = (const float*)d_in[9];
    const float* bo    = (const float*)d_in[10];
    float* out = (float*)d_out;

    __half* S;
    cudaGetSymbolAddress((void**)&S, g_h);
    __half* Qh  = S;
    __half* Kh  = S + 1ull * NX;
    __half* Vth = S + 2ull * NX;
    __half* Ah  = S + 3ull * NX;
    __half* XC  = S + 4ull * NX;        // 3 tensors
    __half* WC  = S + 7ull * NX;        // 4 weights

    Ptr4 xs; xs.p[0] = query; xs.p[1] = key; xs.p[2] = value; xs.p[3] = query;
    Ptr4 ws; ws.p[0] = Wq; ws.p[1] = Wk; ws.p[2] = Wv; ws.p[3] = Wo;

    cvt16_multi<<<dim3(NW / 8 / 256, 4), 256>>>(ws, WC, NW);
    cvt16_multi<<<dim3(NX / 8 / 256, 3), 256>>>(xs, XC, NX);

    cudaFuncSetAttribute(gemm_f16_kernel<0>,
                         cudaFuncAttributeMaxDynamicSharedMemorySize, GEMM_SMEM);
    cudaFuncSetAttribute(gemm_f16_kernel<1>,
                         cudaFuncAttributeMaxDynamicSharedMemorySize, GEMM_SMEM);
    cudaFuncSetAttribute(gemm_f16_kernel<2>,
                         cudaFuncAttributeMaxDynamicSharedMemorySize, GEMM_SMEM);
    cudaFuncSetAttribute(attn_mma_kernel,
                         cudaFuncAttributeMaxDynamicSharedMemorySize, ATTN_SMEM);

    dim3 gg(MTOT / 128, EE / 128);  // 32 x 8
    gemm_f16_kernel<1><<<gg, 128, GEMM_SMEM>>>(XC,             WC,             bq, Qh);
    gemm_f16_kernel<1><<<gg, 128, GEMM_SMEM>>>(XC + NX,        WC + NW,        bk, Kh);
    gemm_f16_kernel<2><<<gg, 128, GEMM_SMEM>>>(XC + 2ull * NX, WC + 2ull * NW, bv, Vth);

    dim3 agrid(SS / 128, BB * HH);  // 16 x 32
    attn_mma_kernel<<<agrid, 256, ATTN_SMEM>>>(Qh, Kh, Vth, Ah);

    gemm_f16_kernel<0><<<gg, 128, GEMM_SMEM>>>(Ah, WC + 3ull * NW, bo, out);
}

// round 11
// speedup vs baseline: 9.1351x; 1.0577x over previous
#include <cuda_runtime.h>
#include <cuda_fp16.h>
#include <cstdint>
#include <math.h>

// Problem constants
#define BB 2
#define SS 2048
#define EE 1024
#define HH 16
#define DD 64
#define MTOT (BB * SS)          // 4096
#define NX (MTOT * EE)          // 4194304 elems per activation tensor
#define NW (EE * EE)            // 1048576 elems per weight

// fp16 scratch arena. Halves:
//  [0,NX)      Qh  [B,H,S,D]
//  [NX,2NX)    Kh  [B,H,S,D]
//  [2NX,3NX)   Vth [B,H,D,S]  (V transposed)
//  [3NX,4NX)   Ah  [B,S,E]    (attention out)
//  [4NX,7NX)   XC  (f16 query,key,value)
//  [7NX,+4NW)  WC  (f16 Wq,Wk,Wv,Wo)
__device__ __half g_h[7ull * NX + 4ull * NW];

// ---------------------------------------------------------------------------
// Helpers (compute_103-safe: mma.sync fp16 + cp.async + ldmatrix)
// ---------------------------------------------------------------------------
__device__ __forceinline__ uint32_t smem_u32(const void* p) {
    uint32_t a;
    asm("{ .reg .u64 t; cvta.to.shared.u64 t, %1; cvt.u32.u64 %0, t; }"
        : "=r"(a) : "l"(p));
    return a;
}
#define CP_ASYNC16(saddr, gptr)                                                \
    asm volatile("cp.async.cg.shared.global [%0], [%1], 16;"                   \
                 :: "r"(saddr), "l"(gptr))
#define CP_COMMIT() asm volatile("cp.async.commit_group;")
#define CP_WAIT(n)  asm volatile("cp.async.wait_group %0;" :: "n"(n))

__device__ __forceinline__ void mma_f16(float c[4], const uint32_t a[4],
                                        const uint32_t b[2]) {
    asm volatile(
        "mma.sync.aligned.m16n8k16.row.col.f32.f16.f16.f32 "
        "{%0,%1,%2,%3}, {%4,%5,%6,%7}, {%8,%9}, {%0,%1,%2,%3};"
        : "+f"(c[0]), "+f"(c[1]), "+f"(c[2]), "+f"(c[3])
        : "r"(a[0]), "r"(a[1]), "r"(a[2]), "r"(a[3]), "r"(b[0]), "r"(b[1]));
}
__device__ __forceinline__ void ldsm_x4(uint32_t& r0, uint32_t& r1,
                                        uint32_t& r2, uint32_t& r3,
                                        uint32_t addr) {
    asm volatile("ldmatrix.sync.aligned.m8n8.x4.shared.b16 {%0,%1,%2,%3}, [%4];"
                 : "=r"(r0), "=r"(r1), "=r"(r2), "=r"(r3) : "r"(addr));
}
__device__ __forceinline__ uint32_t pack_h2(float lo, float hi) {
    __half2 h = __floats2half2_rn(lo, hi);
    return *(uint32_t*)&h;
}
__device__ __forceinline__ uint32_t ldh2(const __half* p) {
    return *(const uint32_t*)p;
}

// ---------------------------------------------------------------------------
// Batched f32 -> f16 conversion: blockIdx.y selects tensor
// ---------------------------------------------------------------------------
struct Ptr4 { const float* p[4]; };

__global__ void __launch_bounds__(256) cvt16_multi(
    Ptr4 srcs, __half* __restrict__ dst, int elems)
{
    const float* x = srcs.p[blockIdx.y];
    __half* y = dst + (size_t)blockIdx.y * elems;
    int i = blockIdx.x * 256 + threadIdx.x;
    float4 a = ((const float4*)x)[2 * i];
    float4 b = ((const float4*)x)[2 * i + 1];
    uint4 u;
    u.x = pack_h2(a.x, a.y); u.y = pack_h2(a.z, a.w);
    u.z = pack_h2(b.x, b.y); u.w = pack_h2(b.z, b.w);
    ((uint4*)y)[i] = u;
}

// ---------------------------------------------------------------------------
// FP16 mma.sync GEMM, 8 warps: C[m,n] = sum_k A[m,k]*W[n,k] + bias[n]
// CTA 128x128, 8 warps (2 x 4), warp tile 64x32. K-chunk 64 (4 k16-steps),
// double-buffered cp.async, 16 chunks. smem stride 72 halves (conflict-free
// ldmatrix). acc = 64 regs/thread -> 2 CTAs/SM at 256 threads.
// MODE 0: C f32 row-major. MODE 1: C f16 [B,H,S,D]. MODE 2: f16 [B,H,D,S].
// ---------------------------------------------------------------------------
#define GSTR 72
#define GTILE_H (128 * GSTR)        // 9216 halves per tile
#define GBUF_H (2 * GTILE_H)        // A+W per buffer
#define GEMM_SMEM (2 * GBUF_H * 2)  // 73728 B

template <int MODE>
__global__ void __launch_bounds__(256, 2) gemm_f16_kernel(
    const __half* __restrict__ A, const __half* __restrict__ W,
    const float* __restrict__ bias, void* __restrict__ Cv)
{
    extern __shared__ __half sh[];

    const int tid  = threadIdx.x;
    const int wid  = tid >> 5;
    const int lane = tid & 31;
    const int g    = lane >> 2;
    const int tk   = lane & 3;
    const int wm   = wid & 1;      // 2 warps over M
    const int wn   = wid >> 1;     // 4 warps over N
    const int m0   = blockIdx.x * 128;
    const int n0   = blockIdx.y * 128;

    const uint32_t sbase = smem_u32(sh);
    const int a_ro = (lane & 7) + ((lane >> 3) & 1) * 8;
    const int a_co = (lane >> 4) * 8;
    const int b_ro = (lane & 7) + (lane >> 4) * 8;
    const int b_co = ((lane >> 3) & 1) * 8;

    float acc[4][4][4];
#pragma unroll
    for (int i = 0; i < 4; ++i)
#pragma unroll
        for (int j = 0; j < 4; ++j)
#pragma unroll
            for (int r = 0; r < 4; ++r) acc[i][j][r] = 0.0f;

    auto issue = [&](int c, int b) {
        const int k0 = c * 64;
        const uint32_t sbuf = sbase + (uint32_t)b * (GBUF_H * 2);
#pragma unroll
        for (int i = 0; i < 8; ++i) {
            const int f = tid + i * 256;          // 0..2047
            if (f < 1024) {
                const int row = f >> 3, c8 = (f & 7) * 8;
                CP_ASYNC16(sbuf + (uint32_t)(row * GSTR + c8) * 2,
                           A + (size_t)(m0 + row) * EE + k0 + c8);
            } else {
                const int f2 = f - 1024;
                const int row = f2 >> 3, c8 = (f2 & 7) * 8;
                CP_ASYNC16(sbuf + (uint32_t)(GTILE_H + row * GSTR + c8) * 2,
                           W + (size_t)(n0 + row) * EE + k0 + c8);
            }
        }
        CP_COMMIT();
    };

    issue(0, 0);

    for (int c = 0; c < 16; ++c) {
        const int buf = c & 1;
        if (c < 15) { issue(c + 1, buf ^ 1); CP_WAIT(1); }
        else        { CP_WAIT(0); }
        __syncthreads();

        const uint32_t Abase = sbase + (uint32_t)buf * (GBUF_H * 2);
        const uint32_t Wbase = Abase + GTILE_H * 2;

#pragma unroll
        for (int ks = 0; ks < 4; ++ks) {
            const int kk = ks * 16;
            uint32_t a[4][4], b[4][2];
#pragma unroll
            for (int i = 0; i < 4; ++i) {
                const uint32_t ad = Abase +
                    (uint32_t)((wm * 64 + i * 16 + a_ro) * GSTR + kk + a_co) * 2;
                ldsm_x4(a[i][0], a[i][1], a[i][2], a[i][3], ad);
            }
#pragma unroll
            for (int jp = 0; jp < 2; ++jp) {
                const uint32_t bd = Wbase +
                    (uint32_t)((wn * 32 + jp * 16 + b_ro) * GSTR + kk + b_co) * 2;
                ldsm_x4(b[2 * jp][0], b[2 * jp][1],
                        b[2 * jp + 1][0], b[2 * jp + 1][1], bd);
            }
#pragma unroll
            for (int i = 0; i < 4; ++i)
#pragma unroll
                for (int j = 0; j < 4; ++j)
                    mma_f16(acc[i][j], a[i], b[j]);
        }
        __syncthreads();
    }

#pragma unroll
    for (int i = 0; i < 4; ++i) {
        const int row0 = m0 + wm * 64 + i * 16 + g;
        const int row1 = row0 + 8;
#pragma unroll
        for (int j = 0; j < 4; ++j) {
            const int col = n0 + wn * 32 + j * 8 + 2 * tk;
            const float b0 = bias[col], b1 = bias[col + 1];
            const float v00 = acc[i][j][0] + b0, v01 = acc[i][j][1] + b1;
            const float v10 = acc[i][j][2] + b0, v11 = acc[i][j][3] + b1;
            if (MODE == 0) {
                float* C = (float*)Cv;
                float2 u0 = {v00, v01}, u1 = {v10, v11};
                *(float2*)&C[(size_t)row0 * EE + col] = u0;
                *(float2*)&C[(size_t)row1 * EE + col] = u1;
            } else if (MODE == 1) {
                __half* C = (__half*)Cv;
                const int h = col >> 6, d = col & 63;
                const int b0r = row0 >> 11, s0 = row0 & (SS - 1);
                const int b1r = row1 >> 11, s1 = row1 & (SS - 1);
                *(uint32_t*)&C[(((size_t)(b0r * HH + h)) * SS + s0) * DD + d] =
                    pack_h2(v00, v01);
                *(uint32_t*)&C[(((size_t)(b1r * HH + h)) * SS + s1) * DD + d] =
                    pack_h2(v10, v11);
            } else {
                __half* C = (__half*)Cv;
                const int h = col >> 6, d = col & 63;
                const int b0r = row0 >> 11, s0 = row0 & (SS - 1);
                const int b1r = row1 >> 11, s1 = row1 & (SS - 1);
                __half* base0 = C + (((size_t)(b0r * HH + h)) * DD + d) * SS;
                __half* base1 = C + (((size_t)(b1r * HH + h)) * DD + d) * SS;
                base0[s0]      = __float2half(v00);
                base0[SS + s0] = __float2half(v01);
                base1[s1]      = __float2half(v10);
                base1[SS + s1] = __float2half(v11);
            }
        }
    }
}

// ---------------------------------------------------------------------------
// FP16 flash attention with ldmatrix fragment loads.
// CTA = 128 query rows of one (b,h), 8 warps x 16 rows. Key tiles of 64,
// double-buffered cp.async. Q frags in registers. K smem [key][dim],
// V^T smem [d][key], both stride 72 halves. QK C-frags ARE PV A-frags.
// launch_bounds(256,2): cap 128 regs -> 2 CTAs/SM.
// ---------------------------------------------------------------------------
#define AST 72
#define ATILE_H (64 * AST)            // 4608 halves per tile
#define ATTN_SMEM (4 * ATILE_H * 2)   // K0,K1,V0,V1 = 36864 B

__global__ void __launch_bounds__(256, 2) attn_mma_kernel(
    const __half* __restrict__ Q, const __half* __restrict__ K,
    const __half* __restrict__ Vt, __half* __restrict__ O)
{
    extern __shared__ __half sh[];
    const int tid  = threadIdx.x;
    const int wid  = tid >> 5;
    const int lane = tid & 31;
    const int g    = lane >> 2;
    const int tk   = lane & 3;
    const int qt   = blockIdx.x;
    const int bh   = blockIdx.y;
    const size_t base = (size_t)bh * SS * DD;

    const uint32_t sb = smem_u32(sh);
    const float Csc = 0.18033688f;     // (1/sqrt(64)) * log2(e)
    const int b_ro = (lane & 7) + (lane >> 4) * 8;
    const int b_co = ((lane >> 3) & 1) * 8;

    uint32_t qf[4][4];
    {
        const __half* Qp = Q + base + (size_t)(qt * 128 + wid * 16) * DD;
#pragma unroll
        for (int ks = 0; ks < 4; ++ks) {
            const int kk = ks * 16 + 2 * tk;
            qf[ks][0] = ldh2(Qp + g * 64 + kk);
            qf[ks][1] = ldh2(Qp + (g + 8) * 64 + kk);
            qf[ks][2] = ldh2(Qp + g * 64 + kk + 8);
            qf[ks][3] = ldh2(Qp + (g + 8) * 64 + kk + 8);
        }
    }

    float oa[8][4];
#pragma unroll
    for (int n = 0; n < 8; ++n)
        oa[n][0] = oa[n][1] = oa[n][2] = oa[n][3] = 0.0f;
    float m0 = -1e30f, m1 = -1e30f, l0 = 0.0f, l1 = 0.0f;

    auto issue = [&](int t, int b) {
        const __half* Kg = K + base + (size_t)t * 64 * DD;
        const __half* Vg = Vt + base + (size_t)t * 64;
        const uint32_t kd = sb + (uint32_t)(b * ATILE_H) * 2;
        const uint32_t vd = sb + (uint32_t)((2 + b) * ATILE_H) * 2;
#pragma unroll
        for (int i = 0; i < 4; ++i) {
            const int f = tid + i * 256;
            if (f < 512) {
                const int row = f >> 3, c8 = (f & 7) * 8;
                CP_ASYNC16(kd + (uint32_t)(row * AST + c8) * 2,
                           Kg + row * 64 + c8);
            } else {
                const int f2 = f - 512;
                const int row = f2 >> 3, c8 = (f2 & 7) * 8;
                CP_ASYNC16(vd + (uint32_t)(row * AST + c8) * 2,
                           Vg + (size_t)row * SS + c8);
            }
        }
        CP_COMMIT();
    };

    issue(0, 0);

    for (int t = 0; t < 32; ++t) {
        const int buf = t & 1;
        if (t < 31) { issue(t + 1, buf ^ 1); CP_WAIT(1); }
        else        { CP_WAIT(0); }
        __syncthreads();

        const uint32_t Kbase = sb + (uint32_t)(buf * ATILE_H) * 2;
        const uint32_t Vbase = sb + (uint32_t)((2 + buf) * ATILE_H) * 2;

        // ---- QK^T ----
        float sa[8][4];
#pragma unroll
        for (int j = 0; j < 8; ++j)
            sa[j][0] = sa[j][1] = sa[j][2] = sa[j][3] = 0.0f;
#pragma unroll
        for (int ks = 0; ks < 4; ++ks) {
            const int kk = ks * 16;
            uint32_t bk[8][2];
#pragma unroll
            for (int jp = 0; jp < 4; ++jp) {
                const uint32_t kdr = Kbase +
                    (uint32_t)((jp * 16 + b_ro) * AST + kk + b_co) * 2;
                ldsm_x4(bk[2 * jp][0], bk[2 * jp][1],
                        bk[2 * jp + 1][0], bk[2 * jp + 1][1], kdr);
            }
#pragma unroll
            for (int j = 0; j < 8; ++j)
                mma_f16(sa[j], qf[ks], bk[j]);
        }

        // ---- online softmax ----
        float rm0 = -1e30f, rm1 = -1e30f;
#pragma unroll
        for (int j = 0; j < 8; ++j) {
            rm0 = fmaxf(rm0, fmaxf(sa[j][0], sa[j][1]));
            rm1 = fmaxf(rm1, fmaxf(sa[j][2], sa[j][3]));
        }
        rm0 = fmaxf(rm0, __shfl_xor_sync(0xffffffffu, rm0, 1));
        rm0 = fmaxf(rm0, __shfl_xor_sync(0xffffffffu, rm0, 2));
        rm1 = fmaxf(rm1, __shfl_xor_sync(0xffffffffu, rm1, 1));
        rm1 = fmaxf(rm1, __shfl_xor_sync(0xffffffffu, rm1, 2));
        const float mn0 = fmaxf(m0, rm0), mn1 = fmaxf(m1, rm1);
        const float al0 = exp2f((m0 - mn0) * Csc);
        const float al1 = exp2f((m1 - mn1) * Csc);
        m0 = mn0; m1 = mn1;

        float s0 = 0.0f, s1 = 0.0f;
#pragma unroll
        for (int j = 0; j < 8; ++j) {
            sa[j][0] = exp2f((sa[j][0] - mn0) * Csc); s0 += sa[j][0];
            sa[j][1] = exp2f((sa[j][1] - mn0) * Csc); s0 += sa[j][1];
            sa[j][2] = exp2f((sa[j][2] - mn1) * Csc); s1 += sa[j][2];
            sa[j][3] = exp2f((sa[j][3] - mn1) * Csc); s1 += sa[j][3];
        }
        s0 += __shfl_xor_sync(0xffffffffu, s0, 1);
        s0 += __shfl_xor_sync(0xffffffffu, s0, 2);
        s1 += __shfl_xor_sync(0xffffffffu, s1, 1);
        s1 += __shfl_xor_sync(0xffffffffu, s1, 2);
        l0 = l0 * al0 + s0;
        l1 = l1 * al1 + s1;
#pragma unroll
        for (int n = 0; n < 8; ++n) {
            oa[n][0] *= al0; oa[n][1] *= al0;
            oa[n][2] *= al1; oa[n][3] *= al1;
        }

        // ---- P: QK C-frag -> fp16 A-frag ----
        uint32_t pa[4][4];
#pragma unroll
        for (int ks = 0; ks < 4; ++ks) {
            pa[ks][0] = pack_h2(sa[2 * ks][0],     sa[2 * ks][1]);
            pa[ks][1] = pack_h2(sa[2 * ks][2],     sa[2 * ks][3]);
            pa[ks][2] = pack_h2(sa[2 * ks + 1][0], sa[2 * ks + 1][1]);
            pa[ks][3] = pack_h2(sa[2 * ks + 1][2], sa[2 * ks + 1][3]);
        }

        // ---- PV ----
#pragma unroll
        for (int ks = 0; ks < 4; ++ks) {
            const int kk = ks * 16;
            uint32_t bv[8][2];
#pragma unroll
            for (int jp = 0; jp < 4; ++jp) {
                const uint32_t vdr = Vbase +
                    (uint32_t)((jp * 16 + b_ro) * AST + kk + b_co) * 2;
                ldsm_x4(bv[2 * jp][0], bv[2 * jp][1],
                        bv[2 * jp + 1][0], bv[2 * jp + 1][1], vdr);
            }
#pragma unroll
            for (int n = 0; n < 8; ++n)
                mma_f16(oa[n], pa[ks], bv[n]);
        }
        __syncthreads();
    }

    // ---- epilogue ----
    const float i0 = 1.0f / l0, i1 = 1.0f / l1;
    const int b = bh >> 4, h = bh & 15;
    const int row0 = qt * 128 + wid * 16 + g;
    const int row1 = row0 + 8;
#pragma unroll
    for (int n = 0; n < 8; ++n) {
        const int col = h * 64 + n * 8 + 2 * tk;
        *(uint32_t*)&O[((size_t)(b * SS + row0)) * EE + col] =
            pack_h2(oa[n][0] * i0, oa[n][1] * i0);
        *(uint32_t*)&O[((size_t)(b * SS + row1)) * EE + col] =
            pack_h2(oa[n][2] * i1, oa[n][3] * i1);
    }
}

// ---------------------------------------------------------------------------
// Launch
// ---------------------------------------------------------------------------
extern "C" void kernel_launch(void* const* d_in, const int* in_sizes, int n_in,
                              void* d_out, int out_size)
{
    const float* query = (const float*)d_in[0];
    const float* key   = (const float*)d_in[1];
    const float* value = (const float*)d_in[2];
    const float* Wq    = (const float*)d_in[3];
    const float* bq    = (const float*)d_in[4];
    const float* Wk    = (const float*)d_in[5];
    const float* bk    = (const float*)d_in[6];
    const float* Wv    = (const float*)d_in[7];
    const float* bv    = (const float*)d_in[8];
    const float* Wo    = (const float*)d_in[9];
    const float* bo    = (const float*)d_in[10];
    float* out = (float*)d_out;

    __half* S;
    cudaGetSymbolAddress((void**)&S, g_h);
    __half* Qh  = S;
    __half* Kh  = S + 1ull * NX;
    __half* Vth = S + 2ull * NX;
    __half* Ah  = S + 3ull * NX;
    __half* XC  = S + 4ull * NX;        // 3 tensors
    __half* WC  = S + 7ull * NX;        // 4 weights

    Ptr4 xs; xs.p[0] = query; xs.p[1] = key; xs.p[2] = value; xs.p[3] = query;
    Ptr4 ws; ws.p[0] = Wq; ws.p[1] = Wk; ws.p[2] = Wv; ws.p[3] = Wo;

    cvt16_multi<<<dim3(NW / 8 / 256, 4), 256>>>(ws, WC, NW);
    cvt16_multi<<<dim3(NX / 8 / 256, 3), 256>>>(xs, XC, NX);

    cudaFuncSetAttribute(gemm_f16_kernel<0>,
                         cudaFuncAttributeMaxDynamicSharedMemorySize, GEMM_SMEM);
    cudaFuncSetAttribute(gemm_f16_kernel<1>,
                         cudaFuncAttributeMaxDynamicSharedMemorySize, GEMM_SMEM);
    cudaFuncSetAttribute(gemm_f16_kernel<2>,
                         cudaFuncAttributeMaxDynamicSharedMemorySize, GEMM_SMEM);
    cudaFuncSetAttribute(attn_mma_kernel,
                         cudaFuncAttributeMaxDynamicSharedMemorySize, ATTN_SMEM);

    dim3 gg(MTOT / 128, EE / 128);  // 32 x 8
    gemm_f16_kernel<1><<<gg, 256, GEMM_SMEM>>>(XC,             WC,             bq, Qh);
    gemm_f16_kernel<1><<<gg, 256, GEMM_SMEM>>>(XC + NX,        WC + NW,        bk, Kh);
    gemm_f16_kernel<2><<<gg, 256, GEMM_SMEM>>>(XC + 2ull * NX, WC + 2ull * NW, bv, Vth);

    dim3 agrid(SS / 128, BB * HH);  // 16 x 32
    attn_mma_kernel<<<agrid, 256, ATTN_SMEM>>>(Qh, Kh, Vth, Ah);

    gemm_f16_kernel<0><<<gg, 256, GEMM_SMEM>>>(Ah, WC + 3ull * NW, bo, out);
}